// round 4
// baseline (speedup 1.0000x reference)
#include <cuda_runtime.h>
#include <cuda_fp16.h>
#include <cstdint>
#include <cstddef>

#define DI __device__ __forceinline__

// ---------------- problem constants ----------------
constexpr int MROWS = 4096;
constexpr int KDIM  = 2048;           // K == N for every GEMM
constexpr int BM = 128, BN = 128, BK = 32;
constexpr int NK = KDIM / BK;         // 64 k-chunks
constexpr int STAGES = 5;
constexpr uint32_t STAGE_BYTES = 4u * 8192u;          // Ah,Al,Bh,Bl tiles (8KB each)
constexpr uint32_t SMEM_DYN = STAGES * STAGE_BYTES + 128;
constexpr int MTILES = MROWS / BM;    // 32
constexpr int NTILES = KDIM / BN;     // 16

// ---------------- device scratch (allocation-free rule) ----------------
__device__ __half g_Ah[2][(size_t)MROWS * KDIM];
__device__ __half g_Al[2][(size_t)MROWS * KDIM];
__device__ __half g_Bh[3][(size_t)KDIM * KDIM];
__device__ __half g_Bl[3][(size_t)KDIM * KDIM];

// ---------------- helpers ----------------
DI uint32_t s2u(const void* p) {
    uint32_t r;
    asm("{ .reg .u64 t; cvta.to.shared.u64 t, %1; cvt.u32.u64 %0, t; }" : "=r"(r) : "l"(p));
    return r;
}
DI void cp16(uint32_t dst, const void* src) {
    asm volatile(
        "{ .reg .u64 g; cvta.to.global.u64 g, %1; cp.async.cg.shared.global [%0], [g], 16; }"
        :: "r"(dst), "l"(src) : "memory");
}
DI void cp_commit() { asm volatile("cp.async.commit_group;" ::: "memory"); }
DI void cp_wait3()  { asm volatile("cp.async.wait_group 3;" ::: "memory"); }

#define LDM4(R0, R1, R2, R3, ADDR) \
    asm volatile("ldmatrix.sync.aligned.m8n8.x4.shared.b16 {%0,%1,%2,%3}, [%4];" \
                 : "=r"(R0), "=r"(R1), "=r"(R2), "=r"(R3) : "r"(ADDR))

#define MMA(C, A, B0, B1) \
    asm volatile("mma.sync.aligned.m16n8k16.row.col.f32.f16.f16.f32 " \
                 "{%0,%1,%2,%3},{%4,%5,%6,%7},{%8,%9},{%0,%1,%2,%3};" \
                 : "+f"((C)[0]), "+f"((C)[1]), "+f"((C)[2]), "+f"((C)[3]) \
                 : "r"((A)[0]), "r"((A)[1]), "r"((A)[2]), "r"((A)[3]), "r"(B0), "r"(B1))

DI void split1(float f, __half& h, __half& l) {
    h = __float2half_rn(f);
    l = __float2half_rn(f - __half2float(h));
}

// ============ prologue: pack concat(x0,x1) -> fp16 hi/lo planes ============
__global__ void pack_x_kernel(const float* __restrict__ x0, const float* __restrict__ x1) {
    int id = blockIdx.x * 256 + threadIdx.x;       // 2M threads, one float4 each
    int m = id >> 9;
    int c4 = (id & 511) * 4;
    const float* s = (c4 < 1024) ? (x0 + (size_t)m * 1024 + c4)
                                 : (x1 + (size_t)m * 1024 + (c4 - 1024));
    float4 v = *(const float4*)s;
    __half h0, h1, h2, h3, l0, l1, l2, l3;
    split1(v.x, h0, l0); split1(v.y, h1, l1);
    split1(v.z, h2, l2); split1(v.w, h3, l3);
    size_t off = (size_t)m * KDIM + c4;
    *(__half2*)(&g_Ah[0][off])     = __halves2half2(h0, h1);
    *(__half2*)(&g_Ah[0][off + 2]) = __halves2half2(h2, h3);
    *(__half2*)(&g_Al[0][off])     = __halves2half2(l0, l1);
    *(__half2*)(&g_Al[0][off + 2]) = __halves2half2(l2, l3);
}

// ============ prologue: W[k][n] -> Bt[n][k] fp16 hi/lo planes ============
__global__ void pack_w_kernel(const float* __restrict__ W0, const float* __restrict__ W1,
                              const float* __restrict__ W2) {
    __shared__ float s[32][33];
    int w = blockIdx.z;
    const float* W = (w == 0) ? W0 : ((w == 1) ? W1 : W2);
    int n0 = blockIdx.x * 32, k0 = blockIdx.y * 32;
    int tx = threadIdx.x, ty = threadIdx.y;  // (32, 8)
#pragma unroll
    for (int i = 0; i < 4; i++)
        s[ty + i * 8][tx] = W[(size_t)(k0 + ty + i * 8) * KDIM + n0 + tx];
    __syncthreads();
#pragma unroll
    for (int i = 0; i < 4; i++) {
        float v = s[tx][ty + i * 8];           // (k_local=tx, n_local=ty+8i)
        __half h, l;
        split1(v, h, l);
        size_t off = (size_t)(n0 + ty + i * 8) * KDIM + k0 + tx;
        g_Bh[w][off] = h;
        g_Bl[w][off] = l;
    }
}

// ============ main GEMM: C = A @ Bt^T via fp16-split 3-product mma.sync ============
template <bool PACK>
__global__ void __launch_bounds__(256, 1)
gemm_kernel(int aset, int wsel, int oset, float* __restrict__ out) {
    extern __shared__ uint8_t smem[];
    uint32_t tiles = (s2u(smem) + 127u) & ~127u;

    const __half* Ah = g_Ah[aset];
    const __half* Al = g_Al[aset];
    const __half* Bh = g_Bh[wsel];
    const __half* Bl = g_Bl[wsel];
    __half* Oh = g_Ah[oset];
    __half* Ol = g_Al[oset];

    int tid = threadIdx.x, lane = tid & 31, wid = tid >> 5;
    int warp_m = wid >> 1, warp_n = wid & 1;            // 4 x 2 warp grid
    int mtile = blockIdx.x & 31, ntile = blockIdx.x >> 5;

    const size_t arow = (size_t)mtile * BM * KDIM;
    const size_t brow = (size_t)ntile * BN * KDIM;

    float c[2][8][4];
#pragma unroll
    for (int a = 0; a < 2; a++)
#pragma unroll
        for (int b = 0; b < 8; b++)
#pragma unroll
            for (int d = 0; d < 4; d++) c[a][b][d] = 0.f;

    // per-chunk loader: 4 planes x 128 rows x 64B, XOR-swizzled 16B chunks
    auto load_chunk = [&](int chunk) {
        if (chunk < NK) {
            uint32_t st = tiles + (uint32_t)(chunk % STAGES) * STAGE_BYTES;
            int kc0 = chunk * BK;
            int cc = tid & 3;
#pragma unroll
            for (int p = 0; p < 8; p++) {
                int plane = p >> 1;
                int r = ((p & 1) << 6) + (tid >> 2);
                const __half* src;
                if (plane == 0)      src = Ah + arow + (size_t)r * KDIM + kc0 + cc * 8;
                else if (plane == 1) src = Al + arow + (size_t)r * KDIM + kc0 + cc * 8;
                else if (plane == 2) src = Bh + brow + (size_t)r * KDIM + kc0 + cc * 8;
                else                 src = Bl + brow + (size_t)r * KDIM + kc0 + cc * 8;
                uint32_t dst = st + (uint32_t)plane * 8192u + (uint32_t)r * 64u +
                               (uint32_t)((cc ^ ((r >> 1) & 3)) << 4);
                cp16(dst, src);
            }
        }
        cp_commit();
    };

#pragma unroll
    for (int c0 = 0; c0 < STAGES - 1; c0++) load_chunk(c0);

    // ldmatrix lane->row/chunk mapping (standard m16n8k16 fragment layouts)
    const int aR = warp_m * 32 + (lane & 7) + ((lane >> 3) & 1) * 8;
    const int aC = lane >> 4;
    const int bR = warp_n * 64 + (lane & 7) + ((lane >> 4) << 3);
    const int bC = (lane >> 3) & 1;

#pragma unroll 1
    for (int k = 0; k < NK; k++) {
        cp_wait3();
        __syncthreads();
        load_chunk(k + STAGES - 1);
        uint32_t st = tiles + (uint32_t)(k % STAGES) * STAGE_BYTES;
#pragma unroll
        for (int ks = 0; ks < 2; ks++) {
            uint32_t ah[2][4], al[2][4], bh[8][2], bl[8][2];
#pragma unroll
            for (int tm = 0; tm < 2; tm++) {
                int row = aR + tm * 16;
                uint32_t cidx = (uint32_t)((ks * 2 + aC) ^ ((row >> 1) & 3));
                uint32_t ad = st + (uint32_t)row * 64u + (cidx << 4);
                LDM4(ah[tm][0], ah[tm][1], ah[tm][2], ah[tm][3], ad);
                LDM4(al[tm][0], al[tm][1], al[tm][2], al[tm][3], ad + 8192u);
            }
#pragma unroll
            for (int p = 0; p < 4; p++) {
                int row = bR + p * 16;
                uint32_t cidx = (uint32_t)((ks * 2 + bC) ^ ((row >> 1) & 3));
                uint32_t bd = st + 16384u + (uint32_t)row * 64u + (cidx << 4);
                uint32_t r0, r1, r2, r3;
                LDM4(r0, r1, r2, r3, bd);
                bh[2 * p][0] = r0; bh[2 * p][1] = r1;
                bh[2 * p + 1][0] = r2; bh[2 * p + 1][1] = r3;
                LDM4(r0, r1, r2, r3, bd + 8192u);
                bl[2 * p][0] = r0; bl[2 * p][1] = r1;
                bl[2 * p + 1][0] = r2; bl[2 * p + 1][1] = r3;
            }
            // ---- 3 passes over 16 independent accumulators: no adjacent RAW ----
#pragma unroll
            for (int tm = 0; tm < 2; tm++)
#pragma unroll
                for (int tn = 0; tn < 8; tn++)
                    MMA(c[tm][tn], ah[tm], bh[tn][0], bh[tn][1]);   // Ah*Bh
#pragma unroll
            for (int tm = 0; tm < 2; tm++)
#pragma unroll
                for (int tn = 0; tn < 8; tn++)
                    MMA(c[tm][tn], al[tm], bh[tn][0], bh[tn][1]);   // Al*Bh
#pragma unroll
            for (int tm = 0; tm < 2; tm++)
#pragma unroll
                for (int tn = 0; tn < 8; tn++)
                    MMA(c[tm][tn], ah[tm], bl[tn][0], bl[tn][1]);   // Ah*Bl
        }
    }

    // ---- epilogue ----
    int r0 = mtile * BM + warp_m * 32 + (lane >> 2);
    int col0 = ntile * BN + warp_n * 64 + (lane & 3) * 2;
#pragma unroll
    for (int tm = 0; tm < 2; tm++)
#pragma unroll
        for (int tn = 0; tn < 8; tn++) {
            int r = r0 + tm * 16, cc = col0 + tn * 8;
            float* v = c[tm][tn];
            if (PACK) {
#pragma unroll
                for (int h = 0; h < 2; h++) {
                    size_t off = (size_t)(r + h * 8) * KDIM + cc;
                    __half h0, h1, l0, l1;
                    split1(v[2 * h], h0, l0);
                    split1(v[2 * h + 1], h1, l1);
                    *(__half2*)(Oh + off) = __halves2half2(h0, h1);
                    *(__half2*)(Ol + off) = __halves2half2(l0, l1);
                }
            } else {
                *(float2*)(out + (size_t)r * KDIM + cc) = make_float2(v[0], v[1]);
                *(float2*)(out + (size_t)(r + 8) * KDIM + cc) = make_float2(v[2], v[3]);
            }
        }
}

// ---------------- launch ----------------
extern "C" void kernel_launch(void* const* d_in, const int* in_sizes, int n_in,
                              void* d_out, int out_size) {
    const float* x0 = (const float*)d_in[0];
    const float* x1 = (const float*)d_in[1];
    const float* W0 = (const float*)d_in[2];
    const float* W1 = (const float*)d_in[3];
    const float* W2 = (const float*)d_in[4];
    float* out = (float*)d_out;

    cudaFuncSetAttribute(gemm_kernel<true>,
                         cudaFuncAttributeMaxDynamicSharedMemorySize, SMEM_DYN);
    cudaFuncSetAttribute(gemm_kernel<false>,
                         cudaFuncAttributeMaxDynamicSharedMemorySize, SMEM_DYN);

    pack_x_kernel<<<8192, 256>>>(x0, x1);
    pack_w_kernel<<<dim3(64, 64, 3), dim3(32, 8)>>>(W0, W1, W2);
    // chain: set0 -> set1 -> set0 -> out
    gemm_kernel<true ><<<MTILES * NTILES, 256, SMEM_DYN>>>(0, 0, 1, nullptr);
    gemm_kernel<true ><<<MTILES * NTILES, 256, SMEM_DYN>>>(1, 1, 0, nullptr);
    gemm_kernel<false><<<MTILES * NTILES, 256, SMEM_DYN>>>(0, 2, 0, out);
}

// round 5
// speedup vs baseline: 1.1939x; 1.1939x over previous
#include <cuda_runtime.h>
#include <cuda_fp16.h>
#include <cstdint>
#include <cstddef>

#define DI __device__ __forceinline__

// ---------------- problem constants ----------------
constexpr int MROWS = 4096;
constexpr int KDIM  = 2048;           // K == N for every GEMM
constexpr int BM = 64, BN = 128, BK = 32;
constexpr int NK = KDIM / BK;         // 64 k-chunks
constexpr int STAGES = 4;
constexpr uint32_t APLANE = BM * 64u;                 // 4096 B
constexpr uint32_t BPLANE = BN * 64u;                 // 8192 B
constexpr uint32_t STAGE_BYTES = 2u * APLANE + 2u * BPLANE;   // 24576
constexpr uint32_t SMEM_DYN = STAGES * STAGE_BYTES + 128;     // ~96KB -> 2 CTAs/SM
constexpr int MTILES = MROWS / BM;    // 64
constexpr int NTILES = KDIM / BN;     // 16

// ---------------- device scratch (allocation-free rule) ----------------
__device__ __half g_Ah[2][(size_t)MROWS * KDIM];
__device__ __half g_Al[2][(size_t)MROWS * KDIM];
__device__ __half g_Bh[3][(size_t)KDIM * KDIM];
__device__ __half g_Bl[3][(size_t)KDIM * KDIM];

// ---------------- helpers ----------------
DI uint32_t s2u(const void* p) {
    uint32_t r;
    asm("{ .reg .u64 t; cvta.to.shared.u64 t, %1; cvt.u32.u64 %0, t; }" : "=r"(r) : "l"(p));
    return r;
}
DI void cp16(uint32_t dst, const void* src) {
    asm volatile(
        "{ .reg .u64 g; cvta.to.global.u64 g, %1; cp.async.cg.shared.global [%0], [g], 16; }"
        :: "r"(dst), "l"(src) : "memory");
}
DI void cp_commit() { asm volatile("cp.async.commit_group;" ::: "memory"); }
DI void cp_wait2()  { asm volatile("cp.async.wait_group 2;" ::: "memory"); }

#define LDM4(R0, R1, R2, R3, ADDR) \
    asm volatile("ldmatrix.sync.aligned.m8n8.x4.shared.b16 {%0,%1,%2,%3}, [%4];" \
                 : "=r"(R0), "=r"(R1), "=r"(R2), "=r"(R3) : "r"(ADDR))

#define MMA(C, A, B0, B1) \
    asm volatile("mma.sync.aligned.m16n8k16.row.col.f32.f16.f16.f32 " \
                 "{%0,%1,%2,%3},{%4,%5,%6,%7},{%8,%9},{%0,%1,%2,%3};" \
                 : "+f"((C)[0]), "+f"((C)[1]), "+f"((C)[2]), "+f"((C)[3]) \
                 : "r"((A)[0]), "r"((A)[1]), "r"((A)[2]), "r"((A)[3]), "r"(B0), "r"(B1))

DI void split1(float f, __half& h, __half& l) {
    h = __float2half_rn(f);
    l = __float2half_rn(f - __half2float(h));
}

// ============ prologue: pack concat(x0,x1) -> fp16 hi/lo planes ============
__global__ void pack_x_kernel(const float* __restrict__ x0, const float* __restrict__ x1) {
    int id = blockIdx.x * 256 + threadIdx.x;       // 2M threads, one float4 each
    int m = id >> 9;
    int c4 = (id & 511) * 4;
    const float* s = (c4 < 1024) ? (x0 + (size_t)m * 1024 + c4)
                                 : (x1 + (size_t)m * 1024 + (c4 - 1024));
    float4 v = *(const float4*)s;
    __half h0, h1, h2, h3, l0, l1, l2, l3;
    split1(v.x, h0, l0); split1(v.y, h1, l1);
    split1(v.z, h2, l2); split1(v.w, h3, l3);
    size_t off = (size_t)m * KDIM + c4;
    *(__half2*)(&g_Ah[0][off])     = __halves2half2(h0, h1);
    *(__half2*)(&g_Ah[0][off + 2]) = __halves2half2(h2, h3);
    *(__half2*)(&g_Al[0][off])     = __halves2half2(l0, l1);
    *(__half2*)(&g_Al[0][off + 2]) = __halves2half2(l2, l3);
}

// ============ prologue: W[k][n] -> Bt[n][k] fp16 hi/lo planes ============
__global__ void pack_w_kernel(const float* __restrict__ W0, const float* __restrict__ W1,
                              const float* __restrict__ W2) {
    __shared__ float s[32][33];
    int w = blockIdx.z;
    const float* W = (w == 0) ? W0 : ((w == 1) ? W1 : W2);
    int n0 = blockIdx.x * 32, k0 = blockIdx.y * 32;
    int tx = threadIdx.x, ty = threadIdx.y;  // (32, 8)
#pragma unroll
    for (int i = 0; i < 4; i++)
        s[ty + i * 8][tx] = W[(size_t)(k0 + ty + i * 8) * KDIM + n0 + tx];
    __syncthreads();
#pragma unroll
    for (int i = 0; i < 4; i++) {
        float v = s[tx][ty + i * 8];           // (k_local=tx, n_local=ty+8i)
        __half h, l;
        split1(v, h, l);
        size_t off = (size_t)(n0 + ty + i * 8) * KDIM + k0 + tx;
        g_Bh[w][off] = h;
        g_Bl[w][off] = l;
    }
}

// ============ main GEMM: C = A @ Bt^T via fp16-split 3-product mma.sync ============
template <bool PACK>
__global__ void __launch_bounds__(256, 2)
gemm_kernel(int aset, int wsel, int oset, float* __restrict__ out) {
    extern __shared__ uint8_t smem[];
    uint32_t tiles = (s2u(smem) + 127u) & ~127u;

    const __half* Ah = g_Ah[aset];
    const __half* Al = g_Al[aset];
    const __half* Bh = g_Bh[wsel];
    const __half* Bl = g_Bl[wsel];
    __half* Oh = g_Ah[oset];
    __half* Ol = g_Al[oset];

    int tid = threadIdx.x, lane = tid & 31, wid = tid >> 5;
    int warp_m = wid >> 2, warp_n = wid & 3;            // 2 x 4 warp grid, 32x32 tiles
    int mtile = blockIdx.x & 63, ntile = blockIdx.x >> 6;

    const size_t arow = (size_t)mtile * BM * KDIM;
    const size_t brow = (size_t)ntile * BN * KDIM;

    float c[2][4][4];
#pragma unroll
    for (int a = 0; a < 2; a++)
#pragma unroll
        for (int b = 0; b < 4; b++)
#pragma unroll
            for (int d = 0; d < 4; d++) c[a][b][d] = 0.f;

    // per-chunk loader: Ah|Al (64 rows) + Bh|Bl (128 rows), 64B/row, swizzled
    const int lr = tid >> 2;         // 0..63
    const int cc = tid & 3;
    auto load_chunk = [&](int chunk) {
        if (chunk < NK) {
            uint32_t st = tiles + (uint32_t)(chunk % STAGES) * STAGE_BYTES;
            const size_t gofs = (size_t)chunk * BK + cc * 8;
            uint32_t sw = (uint32_t)((cc ^ ((lr >> 1) & 3)) << 4);
            uint32_t rowb = (uint32_t)lr * 64u;
            cp16(st + rowb + sw,                    Ah + arow + (size_t)lr * KDIM + gofs);
            cp16(st + APLANE + rowb + sw,           Al + arow + (size_t)lr * KDIM + gofs);
            cp16(st + 2 * APLANE + rowb + sw,       Bh + brow + (size_t)lr * KDIM + gofs);
            cp16(st + 2 * APLANE + BPLANE + rowb + sw, Bl + brow + (size_t)lr * KDIM + gofs);
            int r2 = lr + 64;
            uint32_t sw2 = (uint32_t)((cc ^ ((r2 >> 1) & 3)) << 4);
            uint32_t rowb2 = (uint32_t)r2 * 64u;
            cp16(st + 2 * APLANE + rowb2 + sw2,        Bh + brow + (size_t)r2 * KDIM + gofs);
            cp16(st + 2 * APLANE + BPLANE + rowb2 + sw2, Bl + brow + (size_t)r2 * KDIM + gofs);
        }
        cp_commit();
    };

#pragma unroll
    for (int c0 = 0; c0 < STAGES - 1; c0++) load_chunk(c0);

    // ldmatrix lane->row/chunk mapping (m16n8k16 fragment layouts)
    const int aR = warp_m * 32 + (lane & 7) + ((lane >> 3) & 1) * 8;
    const int aC = lane >> 4;
    const int bR = warp_n * 32 + (lane & 7) + ((lane >> 4) << 3);
    const int bC = (lane >> 3) & 1;

#pragma unroll 1
    for (int k = 0; k < NK; k++) {
        cp_wait2();
        __syncthreads();
        load_chunk(k + STAGES - 1);
        uint32_t st = tiles + (uint32_t)(k % STAGES) * STAGE_BYTES;
#pragma unroll
        for (int ks = 0; ks < 2; ks++) {
            uint32_t ah[2][4], al[2][4], bh[4][2], bl[4][2];
#pragma unroll
            for (int tm = 0; tm < 2; tm++) {
                int row = aR + tm * 16;
                uint32_t cidx = (uint32_t)((ks * 2 + aC) ^ ((row >> 1) & 3));
                uint32_t ad = st + (uint32_t)row * 64u + (cidx << 4);
                LDM4(ah[tm][0], ah[tm][1], ah[tm][2], ah[tm][3], ad);
                LDM4(al[tm][0], al[tm][1], al[tm][2], al[tm][3], ad + APLANE);
            }
#pragma unroll
            for (int p = 0; p < 2; p++) {
                int row = bR + p * 16;
                uint32_t cidx = (uint32_t)((ks * 2 + bC) ^ ((row >> 1) & 3));
                uint32_t bd = st + 2 * APLANE + (uint32_t)row * 64u + (cidx << 4);
                uint32_t r0, r1, r2, r3;
                LDM4(r0, r1, r2, r3, bd);
                bh[2 * p][0] = r0; bh[2 * p][1] = r1;
                bh[2 * p + 1][0] = r2; bh[2 * p + 1][1] = r3;
                LDM4(r0, r1, r2, r3, bd + BPLANE);
                bl[2 * p][0] = r0; bl[2 * p][1] = r1;
                bl[2 * p + 1][0] = r2; bl[2 * p + 1][1] = r3;
            }
#pragma unroll
            for (int tm = 0; tm < 2; tm++)
#pragma unroll
                for (int tn = 0; tn < 4; tn++)
                    MMA(c[tm][tn], ah[tm], bh[tn][0], bh[tn][1]);   // Ah*Bh
#pragma unroll
            for (int tm = 0; tm < 2; tm++)
#pragma unroll
                for (int tn = 0; tn < 4; tn++)
                    MMA(c[tm][tn], al[tm], bh[tn][0], bh[tn][1]);   // Al*Bh
#pragma unroll
            for (int tm = 0; tm < 2; tm++)
#pragma unroll
                for (int tn = 0; tn < 4; tn++)
                    MMA(c[tm][tn], ah[tm], bl[tn][0], bl[tn][1]);   // Ah*Bl
        }
    }

    // ---- epilogue ----
    int r0 = mtile * BM + warp_m * 32 + (lane >> 2);
    int col0 = ntile * BN + warp_n * 32 + (lane & 3) * 2;
#pragma unroll
    for (int tm = 0; tm < 2; tm++)
#pragma unroll
        for (int tn = 0; tn < 4; tn++) {
            int r = r0 + tm * 16, ccc = col0 + tn * 8;
            float* v = c[tm][tn];
            if (PACK) {
#pragma unroll
                for (int h = 0; h < 2; h++) {
                    size_t off = (size_t)(r + h * 8) * KDIM + ccc;
                    __half h0, h1, l0, l1;
                    split1(v[2 * h], h0, l0);
                    split1(v[2 * h + 1], h1, l1);
                    *(__half2*)(Oh + off) = __halves2half2(h0, h1);
                    *(__half2*)(Ol + off) = __halves2half2(l0, l1);
                }
            } else {
                *(float2*)(out + (size_t)r * KDIM + ccc) = make_float2(v[0], v[1]);
                *(float2*)(out + (size_t)(r + 8) * KDIM + ccc) = make_float2(v[2], v[3]);
            }
        }
}

// ---------------- launch ----------------
extern "C" void kernel_launch(void* const* d_in, const int* in_sizes, int n_in,
                              void* d_out, int out_size) {
    const float* x0 = (const float*)d_in[0];
    const float* x1 = (const float*)d_in[1];
    const float* W0 = (const float*)d_in[2];
    const float* W1 = (const float*)d_in[3];
    const float* W2 = (const float*)d_in[4];
    float* out = (float*)d_out;

    cudaFuncSetAttribute(gemm_kernel<true>,
                         cudaFuncAttributeMaxDynamicSharedMemorySize, SMEM_DYN);
    cudaFuncSetAttribute(gemm_kernel<false>,
                         cudaFuncAttributeMaxDynamicSharedMemorySize, SMEM_DYN);

    pack_x_kernel<<<8192, 256>>>(x0, x1);
    pack_w_kernel<<<dim3(64, 64, 3), dim3(32, 8)>>>(W0, W1, W2);
    // chain: set0 -> set1 -> set0 -> out
    gemm_kernel<true ><<<MTILES * NTILES, 256, SMEM_DYN>>>(0, 0, 1, nullptr);
    gemm_kernel<true ><<<MTILES * NTILES, 256, SMEM_DYN>>>(1, 1, 0, nullptr);
    gemm_kernel<false><<<MTILES * NTILES, 256, SMEM_DYN>>>(0, 2, 0, out);
}

// round 6
// speedup vs baseline: 1.4332x; 1.2005x over previous
#include <cuda_runtime.h>
#include <cuda_fp16.h>
#include <cstdint>
#include <cstddef>

#define DI __device__ __forceinline__

// ---------------- problem constants ----------------
constexpr int MROWS = 4096;
constexpr int KDIM  = 2048;           // K == N for every GEMM
constexpr int BM = 64, BN = 128, BK = 32;
constexpr int NK = KDIM / BK;         // 64 k-chunks
constexpr int STAGES = 4;
constexpr uint32_t APLANE = BM * 64u;                 // 4096 B
constexpr uint32_t BPLANE = BN * 64u;                 // 8192 B
constexpr uint32_t STAGE_BYTES = 2u * APLANE + 2u * BPLANE;   // 24576
constexpr uint32_t SMEM_DYN = STAGES * STAGE_BYTES + 128;     // ~96KB -> 2 CTAs/SM
constexpr int MTILES = MROWS / BM;    // 64
constexpr int NTILES = KDIM / BN;     // 16

// ---------------- device scratch (allocation-free rule) ----------------
__device__ __half g_Ah[2][(size_t)MROWS * KDIM];
__device__ __half g_Al[2][(size_t)MROWS * KDIM];
__device__ __half g_Bh[3][(size_t)KDIM * KDIM];
__device__ __half g_Bl[3][(size_t)KDIM * KDIM];

// ---------------- helpers ----------------
DI uint32_t s2u(const void* p) {
    uint32_t r;
    asm("{ .reg .u64 t; cvta.to.shared.u64 t, %1; cvt.u32.u64 %0, t; }" : "=r"(r) : "l"(p));
    return r;
}
DI void cp16(uint32_t dst, const void* src) {
    asm volatile(
        "{ .reg .u64 g; cvta.to.global.u64 g, %1; cp.async.cg.shared.global [%0], [g], 16; }"
        :: "r"(dst), "l"(src) : "memory");
}
DI void cp_commit() { asm volatile("cp.async.commit_group;" ::: "memory"); }
DI void cp_wait1()  { asm volatile("cp.async.wait_group 1;" ::: "memory"); }
DI void cp_wait2()  { asm volatile("cp.async.wait_group 2;" ::: "memory"); }

#define LDM4(R0, R1, R2, R3, ADDR) \
    asm volatile("ldmatrix.sync.aligned.m8n8.x4.shared.b16 {%0,%1,%2,%3}, [%4];" \
                 : "=r"(R0), "=r"(R1), "=r"(R2), "=r"(R3) : "r"(ADDR))

#define MMA(C, A, B0, B1) \
    asm volatile("mma.sync.aligned.m16n8k16.row.col.f32.f16.f16.f32 " \
                 "{%0,%1,%2,%3},{%4,%5,%6,%7},{%8,%9},{%0,%1,%2,%3};" \
                 : "+f"((C)[0]), "+f"((C)[1]), "+f"((C)[2]), "+f"((C)[3]) \
                 : "r"((A)[0]), "r"((A)[1]), "r"((A)[2]), "r"((A)[3]), "r"(B0), "r"(B1))

DI void split1(float f, __half& h, __half& l) {
    h = __float2half_rn(f);
    l = __float2half_rn(f - __half2float(h));
}

// ============ prologue: pack concat(x0,x1) -> fp16 hi/lo planes ============
__global__ void pack_x_kernel(const float* __restrict__ x0, const float* __restrict__ x1) {
    int id = blockIdx.x * 256 + threadIdx.x;       // 2M threads, one float4 each
    int m = id >> 9;
    int c4 = (id & 511) * 4;
    const float* s = (c4 < 1024) ? (x0 + (size_t)m * 1024 + c4)
                                 : (x1 + (size_t)m * 1024 + (c4 - 1024));
    float4 v = *(const float4*)s;
    __half h0, h1, h2, h3, l0, l1, l2, l3;
    split1(v.x, h0, l0); split1(v.y, h1, l1);
    split1(v.z, h2, l2); split1(v.w, h3, l3);
    size_t off = (size_t)m * KDIM + c4;
    *(__half2*)(&g_Ah[0][off])     = __halves2half2(h0, h1);
    *(__half2*)(&g_Ah[0][off + 2]) = __halves2half2(h2, h3);
    *(__half2*)(&g_Al[0][off])     = __halves2half2(l0, l1);
    *(__half2*)(&g_Al[0][off + 2]) = __halves2half2(l2, l3);
}

// ============ prologue: W[k][n] -> Bt[n][k] fp16 hi/lo planes ============
__global__ void pack_w_kernel(const float* __restrict__ W0, const float* __restrict__ W1,
                              const float* __restrict__ W2) {
    __shared__ float s[32][33];
    int w = blockIdx.z;
    const float* W = (w == 0) ? W0 : ((w == 1) ? W1 : W2);
    int n0 = blockIdx.x * 32, k0 = blockIdx.y * 32;
    int tx = threadIdx.x, ty = threadIdx.y;  // (32, 8)
#pragma unroll
    for (int i = 0; i < 4; i++)
        s[ty + i * 8][tx] = W[(size_t)(k0 + ty + i * 8) * KDIM + n0 + tx];
    __syncthreads();
#pragma unroll
    for (int i = 0; i < 4; i++) {
        float v = s[tx][ty + i * 8];           // (k_local=tx, n_local=ty+8i)
        __half h, l;
        split1(v, h, l);
        size_t off = (size_t)(n0 + ty + i * 8) * KDIM + k0 + tx;
        g_Bh[w][off] = h;
        g_Bl[w][off] = l;
    }
}

// ============ main GEMM: C = A @ Bt^T via fp16-split 3-product mma.sync ============
template <bool PACK>
__global__ void __launch_bounds__(256, 2)
gemm_kernel(int aset, int wsel, int oset, float* __restrict__ out) {
    extern __shared__ uint8_t smem[];
    uint32_t tiles = (s2u(smem) + 127u) & ~127u;

    const __half* Ah = g_Ah[aset];
    const __half* Al = g_Al[aset];
    const __half* Bh = g_Bh[wsel];
    const __half* Bl = g_Bl[wsel];
    __half* Oh = g_Ah[oset];
    __half* Ol = g_Al[oset];

    int tid = threadIdx.x, lane = tid & 31, wid = tid >> 5;
    int warp_m = wid >> 2, warp_n = wid & 3;            // 2 x 4 warp grid, 32x32 tiles
    int mtile = blockIdx.x & 63, ntile = blockIdx.x >> 6;

    const size_t arow = (size_t)mtile * BM * KDIM;
    const size_t brow = (size_t)ntile * BN * KDIM;

    float c[2][4][4];
#pragma unroll
    for (int a = 0; a < 2; a++)
#pragma unroll
        for (int b = 0; b < 4; b++)
#pragma unroll
            for (int d = 0; d < 4; d++) c[a][b][d] = 0.f;

    // per-chunk loader: Ah|Al (64 rows) + Bh|Bl (128 rows), 64B/row, swizzled
    const int lr = tid >> 2;         // 0..63
    const int cc = tid & 3;
    auto load_chunk = [&](int chunk) {
        if (chunk < NK) {
            uint32_t st = tiles + (uint32_t)(chunk % STAGES) * STAGE_BYTES;
            const size_t gofs = (size_t)chunk * BK + cc * 8;
            uint32_t sw = (uint32_t)((cc ^ ((lr >> 1) & 3)) << 4);
            uint32_t rowb = (uint32_t)lr * 64u;
            cp16(st + rowb + sw,                    Ah + arow + (size_t)lr * KDIM + gofs);
            cp16(st + APLANE + rowb + sw,           Al + arow + (size_t)lr * KDIM + gofs);
            cp16(st + 2 * APLANE + rowb + sw,       Bh + brow + (size_t)lr * KDIM + gofs);
            cp16(st + 2 * APLANE + BPLANE + rowb + sw, Bl + brow + (size_t)lr * KDIM + gofs);
            int r2 = lr + 64;
            uint32_t sw2 = (uint32_t)((cc ^ ((r2 >> 1) & 3)) << 4);
            uint32_t rowb2 = (uint32_t)r2 * 64u;
            cp16(st + 2 * APLANE + rowb2 + sw2,        Bh + brow + (size_t)r2 * KDIM + gofs);
            cp16(st + 2 * APLANE + BPLANE + rowb2 + sw2, Bl + brow + (size_t)r2 * KDIM + gofs);
        }
        cp_commit();
    };

#pragma unroll
    for (int c0 = 0; c0 < STAGES - 1; c0++) load_chunk(c0);

    // ldmatrix lane->row/chunk mapping (m16n8k16 fragment layouts)
    const int aR = warp_m * 32 + (lane & 7) + ((lane >> 3) & 1) * 8;
    const int aC = lane >> 4;
    const int bR = warp_n * 32 + (lane & 7) + ((lane >> 4) << 3);
    const int bC = (lane >> 3) & 1;

    // double-buffered fragments
    uint32_t ahf[2][2][4], alf[2][2][4], bhf[2][4][2], blf[2][4][2];

    auto ldfrags = [&](int buf, uint32_t st, int ks) {
#pragma unroll
        for (int tm = 0; tm < 2; tm++) {
            int row = aR + tm * 16;
            uint32_t cidx = (uint32_t)((ks * 2 + aC) ^ ((row >> 1) & 3));
            uint32_t ad = st + (uint32_t)row * 64u + (cidx << 4);
            LDM4(ahf[buf][tm][0], ahf[buf][tm][1], ahf[buf][tm][2], ahf[buf][tm][3], ad);
            LDM4(alf[buf][tm][0], alf[buf][tm][1], alf[buf][tm][2], alf[buf][tm][3], ad + APLANE);
        }
#pragma unroll
        for (int p = 0; p < 2; p++) {
            int row = bR + p * 16;
            uint32_t cidx = (uint32_t)((ks * 2 + bC) ^ ((row >> 1) & 3));
            uint32_t bd = st + 2 * APLANE + (uint32_t)row * 64u + (cidx << 4);
            uint32_t r0, r1, r2, r3;
            LDM4(r0, r1, r2, r3, bd);
            bhf[buf][2 * p][0] = r0; bhf[buf][2 * p][1] = r1;
            bhf[buf][2 * p + 1][0] = r2; bhf[buf][2 * p + 1][1] = r3;
            LDM4(r0, r1, r2, r3, bd + BPLANE);
            blf[buf][2 * p][0] = r0; blf[buf][2 * p][1] = r1;
            blf[buf][2 * p + 1][0] = r2; blf[buf][2 * p + 1][1] = r3;
        }
    };

    auto mma_pass = [&](int buf) {
#pragma unroll
        for (int tm = 0; tm < 2; tm++)
#pragma unroll
            for (int tn = 0; tn < 4; tn++)
                MMA(c[tm][tn], ahf[buf][tm], bhf[buf][tn][0], bhf[buf][tn][1]);   // Ah*Bh
#pragma unroll
        for (int tm = 0; tm < 2; tm++)
#pragma unroll
            for (int tn = 0; tn < 4; tn++)
                MMA(c[tm][tn], alf[buf][tm], bhf[buf][tn][0], bhf[buf][tn][1]);   // Al*Bh
#pragma unroll
        for (int tm = 0; tm < 2; tm++)
#pragma unroll
            for (int tn = 0; tn < 4; tn++)
                MMA(c[tm][tn], ahf[buf][tm], blf[buf][tn][0], blf[buf][tn][1]);   // Ah*Bl
    };

    cp_wait2();             // chunk 0 arrived (3 groups committed, <=2 pending)
    __syncthreads();
    ldfrags(0, tiles, 0);   // chunk 0, ks=0

#pragma unroll 1
    for (int k = 0; k < NK; k++) {
        uint32_t st = tiles + (uint32_t)(k % STAGES) * STAGE_BYTES;
        ldfrags(1, st, 1);              // ks=1 frags: overlaps with buf0 MMAs below
        mma_pass(0);
        cp_wait1();                     // chunk k+1 arrived
        __syncthreads();                // all warps done reading chunk k-1 stage
        load_chunk(k + STAGES - 1);     // refill stage (k-1)%4 with chunk k+3
        if (k + 1 < NK) {
            uint32_t st2 = tiles + (uint32_t)((k + 1) % STAGES) * STAGE_BYTES;
            ldfrags(0, st2, 0);         // prefetch next chunk ks=0: overlaps buf1 MMAs
        }
        mma_pass(1);
    }

    // ---- epilogue ----
    int r0 = mtile * BM + warp_m * 32 + (lane >> 2);
    int col0 = ntile * BN + warp_n * 32 + (lane & 3) * 2;
#pragma unroll
    for (int tm = 0; tm < 2; tm++)
#pragma unroll
        for (int tn = 0; tn < 4; tn++) {
            int r = r0 + tm * 16, ccc = col0 + tn * 8;
            float* v = c[tm][tn];
            if (PACK) {
#pragma unroll
                for (int h = 0; h < 2; h++) {
                    size_t off = (size_t)(r + h * 8) * KDIM + ccc;
                    __half h0, h1, l0, l1;
                    split1(v[2 * h], h0, l0);
                    split1(v[2 * h + 1], h1, l1);
                    *(__half2*)(Oh + off) = __halves2half2(h0, h1);
                    *(__half2*)(Ol + off) = __halves2half2(l0, l1);
                }
            } else {
                *(float2*)(out + (size_t)r * KDIM + ccc) = make_float2(v[0], v[1]);
                *(float2*)(out + (size_t)(r + 8) * KDIM + ccc) = make_float2(v[2], v[3]);
            }
        }
}

// ---------------- launch ----------------
extern "C" void kernel_launch(void* const* d_in, const int* in_sizes, int n_in,
                              void* d_out, int out_size) {
    const float* x0 = (const float*)d_in[0];
    const float* x1 = (const float*)d_in[1];
    const float* W0 = (const float*)d_in[2];
    const float* W1 = (const float*)d_in[3];
    const float* W2 = (const float*)d_in[4];
    float* out = (float*)d_out;

    cudaFuncSetAttribute(gemm_kernel<true>,
                         cudaFuncAttributeMaxDynamicSharedMemorySize, SMEM_DYN);
    cudaFuncSetAttribute(gemm_kernel<false>,
                         cudaFuncAttributeMaxDynamicSharedMemorySize, SMEM_DYN);

    pack_x_kernel<<<8192, 256>>>(x0, x1);
    pack_w_kernel<<<dim3(64, 64, 3), dim3(32, 8)>>>(W0, W1, W2);
    // chain: set0 -> set1 -> set0 -> out
    gemm_kernel<true ><<<MTILES * NTILES, 256, SMEM_DYN>>>(0, 0, 1, nullptr);
    gemm_kernel<true ><<<MTILES * NTILES, 256, SMEM_DYN>>>(1, 1, 0, nullptr);
    gemm_kernel<false><<<MTILES * NTILES, 256, SMEM_DYN>>>(0, 2, 0, out);
}

// round 7
// speedup vs baseline: 1.9411x; 1.3543x over previous
#include <cuda_runtime.h>
#include <cuda_fp16.h>
#include <cstdint>
#include <cstddef>

#define DI __device__ __forceinline__

// ---------------- problem constants ----------------
constexpr int MROWS = 4096;
constexpr int KDIM  = 2048;           // K == N for every GEMM
constexpr int BM = 64, BN = 128, BK = 32;
constexpr int NK = KDIM / BK;         // 64 k-chunks
constexpr int STAGES = 4;
constexpr uint32_t APLANE = BM * 64u;                 // 4096 B
constexpr uint32_t BPLANE = BN * 64u;                 // 8192 B
constexpr uint32_t STAGE_BYTES = 2u * APLANE + 2u * BPLANE;   // 24576
constexpr uint32_t SMEM_DYN = STAGES * STAGE_BYTES + 128;     // ~96KB -> 2 CTAs/SM

// ---------------- plane pool (identical A-side / B-side / output format) ----------------
constexpr size_t MEG = 1024ull * 1024ull;
constexpr size_t OFF_X  = 0;          // X = concat(x0,x1)   [4096 x 2048]
constexpr size_t OFF_A0 = 8 * MEG;    // W0 row-major        [2048 x 2048]
constexpr size_t OFF_B1 = 12 * MEG;   // W1^T                [2048 x 2048]
constexpr size_t OFF_A2 = 16 * MEG;   // W2^T                [2048 x 2048]
constexpr size_t OFF_P1 = 20 * MEG;   // P1 = W0*W1          [2048 x 2048]
constexpr size_t OFF_Q  = 24 * MEG;   // Q  = (W0*W1*W2)^T   [2048 x 2048]
constexpr size_t POOL   = 28 * MEG;

__device__ __half g_H[POOL];          // hi planes
__device__ __half g_L[POOL];          // lo planes

// ---------------- helpers ----------------
DI uint32_t s2u(const void* p) {
    uint32_t r;
    asm("{ .reg .u64 t; cvta.to.shared.u64 t, %1; cvt.u32.u64 %0, t; }" : "=r"(r) : "l"(p));
    return r;
}
DI void cp16(uint32_t dst, const void* src) {
    asm volatile(
        "{ .reg .u64 g; cvta.to.global.u64 g, %1; cp.async.cg.shared.global [%0], [g], 16; }"
        :: "r"(dst), "l"(src) : "memory");
}
DI void cp_commit() { asm volatile("cp.async.commit_group;" ::: "memory"); }
DI void cp_wait1()  { asm volatile("cp.async.wait_group 1;" ::: "memory"); }
DI void cp_wait2()  { asm volatile("cp.async.wait_group 2;" ::: "memory"); }

#define LDM4(R0, R1, R2, R3, ADDR) \
    asm volatile("ldmatrix.sync.aligned.m8n8.x4.shared.b16 {%0,%1,%2,%3}, [%4];" \
                 : "=r"(R0), "=r"(R1), "=r"(R2), "=r"(R3) : "r"(ADDR))

#define MMA(C, A, B0, B1) \
    asm volatile("mma.sync.aligned.m16n8k16.row.col.f32.f16.f16.f32 " \
                 "{%0,%1,%2,%3},{%4,%5,%6,%7},{%8,%9},{%0,%1,%2,%3};" \
                 : "+f"((C)[0]), "+f"((C)[1]), "+f"((C)[2]), "+f"((C)[3]) \
                 : "r"((A)[0]), "r"((A)[1]), "r"((A)[2]), "r"((A)[3]), "r"(B0), "r"(B1))

DI void split1(float f, __half& h, __half& l) {
    h = __float2half_rn(f);
    l = __float2half_rn(f - __half2float(h));
}

// ============ prologue: pack concat(x0,x1) -> planes @ OFF_X ============
__global__ void pack_x_kernel(const float* __restrict__ x0, const float* __restrict__ x1) {
    int id = blockIdx.x * 256 + threadIdx.x;       // 2M threads, one float4 each
    int m = id >> 9;
    int c4 = (id & 511) * 4;
    const float* s = (c4 < 1024) ? (x0 + (size_t)m * 1024 + c4)
                                 : (x1 + (size_t)m * 1024 + (c4 - 1024));
    float4 v = *(const float4*)s;
    __half h0, h1, h2, h3, l0, l1, l2, l3;
    split1(v.x, h0, l0); split1(v.y, h1, l1);
    split1(v.z, h2, l2); split1(v.w, h3, l3);
    size_t off = OFF_X + (size_t)m * KDIM + c4;
    *(__half2*)(&g_H[off])     = __halves2half2(h0, h1);
    *(__half2*)(&g_H[off + 2]) = __halves2half2(h2, h3);
    *(__half2*)(&g_L[off])     = __halves2half2(l0, l1);
    *(__half2*)(&g_L[off + 2]) = __halves2half2(l2, l3);
}

// ============ prologue: row-major pack (W0) -> planes @ dstoff ============
__global__ void pack_rm_kernel(const float* __restrict__ src, size_t dstoff) {
    int id = blockIdx.x * 256 + threadIdx.x;       // 1M threads (2048x2048/4)
    int m = id >> 9;
    int c4 = (id & 511) * 4;
    float4 v = *(const float4*)(src + (size_t)m * KDIM + c4);
    __half h0, h1, h2, h3, l0, l1, l2, l3;
    split1(v.x, h0, l0); split1(v.y, h1, l1);
    split1(v.z, h2, l2); split1(v.w, h3, l3);
    size_t off = dstoff + (size_t)m * KDIM + c4;
    *(__half2*)(&g_H[off])     = __halves2half2(h0, h1);
    *(__half2*)(&g_H[off + 2]) = __halves2half2(h2, h3);
    *(__half2*)(&g_L[off])     = __halves2half2(l0, l1);
    *(__half2*)(&g_L[off + 2]) = __halves2half2(l2, l3);
}

// ============ prologue: transposed pack (W^T) -> planes @ dstoff ============
__global__ void pack_wt_kernel(const float* __restrict__ W, size_t dstoff) {
    __shared__ float s[32][33];
    int n0 = blockIdx.x * 32, k0 = blockIdx.y * 32;
    int tx = threadIdx.x, ty = threadIdx.y;  // (32, 8)
#pragma unroll
    for (int i = 0; i < 4; i++)
        s[ty + i * 8][tx] = W[(size_t)(k0 + ty + i * 8) * KDIM + n0 + tx];
    __syncthreads();
#pragma unroll
    for (int i = 0; i < 4; i++) {
        float v = s[tx][ty + i * 8];           // (k_local=tx, n_local=ty+8i)
        __half h, l;
        split1(v, h, l);
        size_t off = dstoff + (size_t)(n0 + ty + i * 8) * KDIM + k0 + tx;
        g_H[off] = h;
        g_L[off] = l;
    }
}

// ============ main GEMM: C = A @ Bt^T via fp16-split 3-product mma.sync ============
template <bool PACK, int MSHIFT>
__global__ void __launch_bounds__(256, 2)
gemm_kernel(size_t aoff, size_t boff, size_t ooff, float* __restrict__ out) {
    extern __shared__ uint8_t smem[];
    uint32_t tiles = (s2u(smem) + 127u) & ~127u;

    const __half* Ah = g_H + aoff;
    const __half* Al = g_L + aoff;
    const __half* Bh = g_H + boff;
    const __half* Bl = g_L + boff;
    __half* Oh = g_H + ooff;
    __half* Ol = g_L + ooff;

    int tid = threadIdx.x, lane = tid & 31, wid = tid >> 5;
    int warp_m = wid >> 2, warp_n = wid & 3;            // 2 x 4 warp grid, 32x32 tiles
    int mtile = blockIdx.x & ((1 << MSHIFT) - 1), ntile = blockIdx.x >> MSHIFT;

    const size_t arow = (size_t)mtile * BM * KDIM;
    const size_t brow = (size_t)ntile * BN * KDIM;

    float c[2][4][4];
#pragma unroll
    for (int a = 0; a < 2; a++)
#pragma unroll
        for (int b = 0; b < 4; b++)
#pragma unroll
            for (int d = 0; d < 4; d++) c[a][b][d] = 0.f;

    // per-chunk loader: Ah|Al (64 rows) + Bh|Bl (128 rows), 64B/row, swizzled
    const int lr = tid >> 2;         // 0..63
    const int cc = tid & 3;
    auto load_chunk = [&](int chunk) {
        if (chunk < NK) {
            uint32_t st = tiles + (uint32_t)(chunk % STAGES) * STAGE_BYTES;
            const size_t gofs = (size_t)chunk * BK + cc * 8;
            uint32_t sw = (uint32_t)((cc ^ ((lr >> 1) & 3)) << 4);
            uint32_t rowb = (uint32_t)lr * 64u;
            cp16(st + rowb + sw,                    Ah + arow + (size_t)lr * KDIM + gofs);
            cp16(st + APLANE + rowb + sw,           Al + arow + (size_t)lr * KDIM + gofs);
            cp16(st + 2 * APLANE + rowb + sw,       Bh + brow + (size_t)lr * KDIM + gofs);
            cp16(st + 2 * APLANE + BPLANE + rowb + sw, Bl + brow + (size_t)lr * KDIM + gofs);
            int r2 = lr + 64;
            uint32_t sw2 = (uint32_t)((cc ^ ((r2 >> 1) & 3)) << 4);
            uint32_t rowb2 = (uint32_t)r2 * 64u;
            cp16(st + 2 * APLANE + rowb2 + sw2,        Bh + brow + (size_t)r2 * KDIM + gofs);
            cp16(st + 2 * APLANE + BPLANE + rowb2 + sw2, Bl + brow + (size_t)r2 * KDIM + gofs);
        }
        cp_commit();
    };

#pragma unroll
    for (int c0 = 0; c0 < STAGES - 1; c0++) load_chunk(c0);

    // ldmatrix lane->row/chunk mapping (m16n8k16 fragment layouts)
    const int aR = warp_m * 32 + (lane & 7) + ((lane >> 3) & 1) * 8;
    const int aC = lane >> 4;
    const int bR = warp_n * 32 + (lane & 7) + ((lane >> 4) << 3);
    const int bC = (lane >> 3) & 1;

    // double-buffered fragments
    uint32_t ahf[2][2][4], alf[2][2][4], bhf[2][4][2], blf[2][4][2];

    auto ldfrags = [&](int buf, uint32_t st, int ks) {
#pragma unroll
        for (int tm = 0; tm < 2; tm++) {
            int row = aR + tm * 16;
            uint32_t cidx = (uint32_t)((ks * 2 + aC) ^ ((row >> 1) & 3));
            uint32_t ad = st + (uint32_t)row * 64u + (cidx << 4);
            LDM4(ahf[buf][tm][0], ahf[buf][tm][1], ahf[buf][tm][2], ahf[buf][tm][3], ad);
            LDM4(alf[buf][tm][0], alf[buf][tm][1], alf[buf][tm][2], alf[buf][tm][3], ad + APLANE);
        }
#pragma unroll
        for (int p = 0; p < 2; p++) {
            int row = bR + p * 16;
            uint32_t cidx = (uint32_t)((ks * 2 + bC) ^ ((row >> 1) & 3));
            uint32_t bd = st + 2 * APLANE + (uint32_t)row * 64u + (cidx << 4);
            uint32_t r0, r1, r2, r3;
            LDM4(r0, r1, r2, r3, bd);
            bhf[buf][2 * p][0] = r0; bhf[buf][2 * p][1] = r1;
            bhf[buf][2 * p + 1][0] = r2; bhf[buf][2 * p + 1][1] = r3;
            LDM4(r0, r1, r2, r3, bd + BPLANE);
            blf[buf][2 * p][0] = r0; blf[buf][2 * p][1] = r1;
            blf[buf][2 * p + 1][0] = r2; blf[buf][2 * p + 1][1] = r3;
        }
    };

    auto mma_pass = [&](int buf) {
#pragma unroll
        for (int tm = 0; tm < 2; tm++)
#pragma unroll
            for (int tn = 0; tn < 4; tn++)
                MMA(c[tm][tn], ahf[buf][tm], bhf[buf][tn][0], bhf[buf][tn][1]);   // Ah*Bh
#pragma unroll
        for (int tm = 0; tm < 2; tm++)
#pragma unroll
            for (int tn = 0; tn < 4; tn++)
                MMA(c[tm][tn], alf[buf][tm], bhf[buf][tn][0], bhf[buf][tn][1]);   // Al*Bh
#pragma unroll
        for (int tm = 0; tm < 2; tm++)
#pragma unroll
            for (int tn = 0; tn < 4; tn++)
                MMA(c[tm][tn], ahf[buf][tm], blf[buf][tn][0], blf[buf][tn][1]);   // Ah*Bl
    };

    cp_wait2();             // chunk 0 arrived (3 groups committed, <=2 pending)
    __syncthreads();
    ldfrags(0, tiles, 0);   // chunk 0, ks=0

#pragma unroll 1
    for (int k = 0; k < NK; k++) {
        uint32_t st = tiles + (uint32_t)(k % STAGES) * STAGE_BYTES;
        ldfrags(1, st, 1);              // ks=1 frags: overlaps with buf0 MMAs below
        mma_pass(0);
        cp_wait1();                     // chunk k+1 arrived
        __syncthreads();                // all warps done reading chunk k-1 stage
        load_chunk(k + STAGES - 1);     // refill stage (k-1)%4 with chunk k+3
        if (k + 1 < NK) {
            uint32_t st2 = tiles + (uint32_t)((k + 1) % STAGES) * STAGE_BYTES;
            ldfrags(0, st2, 0);         // prefetch next chunk ks=0: overlaps buf1 MMAs
        }
        mma_pass(1);
    }

    // ---- epilogue ----
    int r0 = mtile * BM + warp_m * 32 + (lane >> 2);
    int col0 = ntile * BN + warp_n * 32 + (lane & 3) * 2;
#pragma unroll
    for (int tm = 0; tm < 2; tm++)
#pragma unroll
        for (int tn = 0; tn < 4; tn++) {
            int r = r0 + tm * 16, ccc = col0 + tn * 8;
            float* v = c[tm][tn];
            if (PACK) {
#pragma unroll
                for (int h = 0; h < 2; h++) {
                    size_t off = (size_t)(r + h * 8) * KDIM + ccc;
                    __half h0, h1, l0, l1;
                    split1(v[2 * h], h0, l0);
                    split1(v[2 * h + 1], h1, l1);
                    *(__half2*)(Oh + off) = __halves2half2(h0, h1);
                    *(__half2*)(Ol + off) = __halves2half2(l0, l1);
                }
            } else {
                *(float2*)(out + (size_t)r * KDIM + ccc) = make_float2(v[0], v[1]);
                *(float2*)(out + (size_t)(r + 8) * KDIM + ccc) = make_float2(v[2], v[3]);
            }
        }
}

// ---------------- launch ----------------
// out = X * (W0*W1*W2):
//   P1 = W0 * W1                 (A = W0 row-major,  B = W1^T)
//   Q  = (P1*W2)^T  via  Q[j][k2] = sum_t W2^T[j][t] * P1[k2][t]   (A = W2^T, B = P1)
//   out = X * Wc    via  out[i][j] = sum_k2 X[i][k2] * Q[j][k2]    (A = X,    B = Q)
extern "C" void kernel_launch(void* const* d_in, const int* in_sizes, int n_in,
                              void* d_out, int out_size) {
    const float* x0 = (const float*)d_in[0];
    const float* x1 = (const float*)d_in[1];
    const float* W0 = (const float*)d_in[2];
    const float* W1 = (const float*)d_in[3];
    const float* W2 = (const float*)d_in[4];
    float* out = (float*)d_out;

    cudaFuncSetAttribute(gemm_kernel<true, 5>,
                         cudaFuncAttributeMaxDynamicSharedMemorySize, SMEM_DYN);
    cudaFuncSetAttribute(gemm_kernel<false, 6>,
                         cudaFuncAttributeMaxDynamicSharedMemorySize, SMEM_DYN);

    pack_x_kernel<<<8192, 256>>>(x0, x1);
    pack_rm_kernel<<<4096, 256>>>(W0, OFF_A0);
    pack_wt_kernel<<<dim3(64, 64), dim3(32, 8)>>>(W1, OFF_B1);
    pack_wt_kernel<<<dim3(64, 64), dim3(32, 8)>>>(W2, OFF_A2);

    gemm_kernel<true, 5><<<32 * 16, 256, SMEM_DYN>>>(OFF_A0, OFF_B1, OFF_P1, nullptr);
    gemm_kernel<true, 5><<<32 * 16, 256, SMEM_DYN>>>(OFF_A2, OFF_P1, OFF_Q, nullptr);
    gemm_kernel<false, 6><<<64 * 16, 256, SMEM_DYN>>>(OFF_X, OFF_Q, 0, out);
}

// round 8
// speedup vs baseline: 2.7403x; 1.4117x over previous
#include <cuda_runtime.h>
#include <cuda_fp16.h>
#include <cstdint>
#include <cstddef>

#define DI __device__ __forceinline__

// ---------------- problem constants ----------------
constexpr int MROWS = 4096;
constexpr int KDIM  = 2048;           // K == N for every GEMM
constexpr int BM = 64, BN = 128, BK = 32;
constexpr int NK = KDIM / BK;         // 64 k-chunks
constexpr int STAGES = 4;
constexpr uint32_t APLANE = BM * 64u;                 // 4096 B
constexpr uint32_t BPLANE = BN * 64u;                 // 8192 B
constexpr uint32_t STAGE_BYTES = 2u * APLANE + BPLANE;        // 16384 (Ah,Al,Bh)
constexpr uint32_t SMEM_DYN = STAGES * STAGE_BYTES + 128;     // ~64KB -> 2 CTAs/SM

// ---------------- plane pool ----------------
// A-side tensors keep hi+lo planes; B-side tensors are single fp16 (hi plane only).
constexpr size_t MEG = 1024ull * 1024ull;
constexpr size_t OFF_X  = 0;          // X = concat(x0,x1)   [4096 x 2048]  A-side (hi+lo)
constexpr size_t OFF_A0 = 8 * MEG;    // W0 row-major        [2048 x 2048]  A-side (hi+lo)
constexpr size_t OFF_B1 = 12 * MEG;   // W1^T                [2048 x 2048]  B-side (hi)
constexpr size_t OFF_A2 = 16 * MEG;   // W2^T                [2048 x 2048]  A-side (hi+lo)
constexpr size_t OFF_P1 = 20 * MEG;   // P1 = W0*W1          [2048 x 2048]  B-side (hi)
constexpr size_t OFF_Q  = 24 * MEG;   // Q  = (W0*W1*W2)^T   [2048 x 2048]  B-side (hi)
constexpr size_t POOL   = 28 * MEG;

__device__ __half g_H[POOL];          // hi planes
__device__ __half g_L[POOL];          // lo planes (A-side tensors only)

// ---------------- helpers ----------------
DI uint32_t s2u(const void* p) {
    uint32_t r;
    asm("{ .reg .u64 t; cvta.to.shared.u64 t, %1; cvt.u32.u64 %0, t; }" : "=r"(r) : "l"(p));
    return r;
}
DI void cp16(uint32_t dst, const void* src) {
    asm volatile(
        "{ .reg .u64 g; cvta.to.global.u64 g, %1; cp.async.cg.shared.global [%0], [g], 16; }"
        :: "r"(dst), "l"(src) : "memory");
}
DI void cp_commit() { asm volatile("cp.async.commit_group;" ::: "memory"); }
DI void cp_wait1()  { asm volatile("cp.async.wait_group 1;" ::: "memory"); }
DI void cp_wait2()  { asm volatile("cp.async.wait_group 2;" ::: "memory"); }

#define LDM4(R0, R1, R2, R3, ADDR) \
    asm volatile("ldmatrix.sync.aligned.m8n8.x4.shared.b16 {%0,%1,%2,%3}, [%4];" \
                 : "=r"(R0), "=r"(R1), "=r"(R2), "=r"(R3) : "r"(ADDR))

#define MMA(C, A, B0, B1) \
    asm volatile("mma.sync.aligned.m16n8k16.row.col.f32.f16.f16.f32 " \
                 "{%0,%1,%2,%3},{%4,%5,%6,%7},{%8,%9},{%0,%1,%2,%3};" \
                 : "+f"((C)[0]), "+f"((C)[1]), "+f"((C)[2]), "+f"((C)[3]) \
                 : "r"((A)[0]), "r"((A)[1]), "r"((A)[2]), "r"((A)[3]), "r"(B0), "r"(B1))

DI void split1(float f, __half& h, __half& l) {
    h = __float2half_rn(f);
    l = __float2half_rn(f - __half2float(h));
}

// ============ prologue: pack concat(x0,x1) -> hi+lo planes @ OFF_X ============
__global__ void pack_x_kernel(const float* __restrict__ x0, const float* __restrict__ x1) {
    int id = blockIdx.x * 256 + threadIdx.x;       // 2M threads, one float4 each
    int m = id >> 9;
    int c4 = (id & 511) * 4;
    const float* s = (c4 < 1024) ? (x0 + (size_t)m * 1024 + c4)
                                 : (x1 + (size_t)m * 1024 + (c4 - 1024));
    float4 v = *(const float4*)s;
    __half h0, h1, h2, h3, l0, l1, l2, l3;
    split1(v.x, h0, l0); split1(v.y, h1, l1);
    split1(v.z, h2, l2); split1(v.w, h3, l3);
    size_t off = OFF_X + (size_t)m * KDIM + c4;
    *(__half2*)(&g_H[off])     = __halves2half2(h0, h1);
    *(__half2*)(&g_H[off + 2]) = __halves2half2(h2, h3);
    *(__half2*)(&g_L[off])     = __halves2half2(l0, l1);
    *(__half2*)(&g_L[off + 2]) = __halves2half2(l2, l3);
}

// ============ prologue: row-major pack (W0) -> hi+lo planes @ dstoff ============
__global__ void pack_rm_kernel(const float* __restrict__ src, size_t dstoff) {
    int id = blockIdx.x * 256 + threadIdx.x;       // 1M threads (2048x2048/4)
    int m = id >> 9;
    int c4 = (id & 511) * 4;
    float4 v = *(const float4*)(src + (size_t)m * KDIM + c4);
    __half h0, h1, h2, h3, l0, l1, l2, l3;
    split1(v.x, h0, l0); split1(v.y, h1, l1);
    split1(v.z, h2, l2); split1(v.w, h3, l3);
    size_t off = dstoff + (size_t)m * KDIM + c4;
    *(__half2*)(&g_H[off])     = __halves2half2(h0, h1);
    *(__half2*)(&g_H[off + 2]) = __halves2half2(h2, h3);
    *(__half2*)(&g_L[off])     = __halves2half2(l0, l1);
    *(__half2*)(&g_L[off + 2]) = __halves2half2(l2, l3);
}

// ============ prologue: transposed pack (W^T) -> planes @ dstoff ============
template <bool WITHLO>
__global__ void pack_wt_kernel(const float* __restrict__ W, size_t dstoff) {
    __shared__ float s[32][33];
    int n0 = blockIdx.x * 32, k0 = blockIdx.y * 32;
    int tx = threadIdx.x, ty = threadIdx.y;  // (32, 8)
#pragma unroll
    for (int i = 0; i < 4; i++)
        s[ty + i * 8][tx] = W[(size_t)(k0 + ty + i * 8) * KDIM + n0 + tx];
    __syncthreads();
#pragma unroll
    for (int i = 0; i < 4; i++) {
        float v = s[tx][ty + i * 8];           // (k_local=tx, n_local=ty+8i)
        __half h, l;
        split1(v, h, l);
        size_t off = dstoff + (size_t)(n0 + ty + i * 8) * KDIM + k0 + tx;
        g_H[off] = h;
        if (WITHLO) g_L[off] = l;
    }
}

// ============ main GEMM: C = (Ah+Al) @ Bh^T  (2-product fp16-split mma.sync) ============
template <bool PACK, int MSHIFT>
__global__ void __launch_bounds__(256, 2)
gemm_kernel(size_t aoff, size_t boff, size_t ooff, float* __restrict__ out) {
    extern __shared__ uint8_t smem[];
    uint32_t tiles = (s2u(smem) + 127u) & ~127u;

    const __half* Ah = g_H + aoff;
    const __half* Al = g_L + aoff;
    const __half* Bh = g_H + boff;
    __half* Oh = g_H + ooff;

    int tid = threadIdx.x, lane = tid & 31, wid = tid >> 5;
    int warp_m = wid >> 2, warp_n = wid & 3;            // 2 x 4 warp grid, 32x32 tiles
    int mtile = blockIdx.x & ((1 << MSHIFT) - 1), ntile = blockIdx.x >> MSHIFT;

    const size_t arow = (size_t)mtile * BM * KDIM;
    const size_t brow = (size_t)ntile * BN * KDIM;

    float c[2][4][4];
#pragma unroll
    for (int a = 0; a < 2; a++)
#pragma unroll
        for (int b = 0; b < 4; b++)
#pragma unroll
            for (int d = 0; d < 4; d++) c[a][b][d] = 0.f;

    // per-chunk loader: Ah|Al (64 rows each) + Bh (128 rows), 64B/row, swizzled
    const int lr = tid >> 2;         // 0..63
    const int cc = tid & 3;
    auto load_chunk = [&](int chunk) {
        if (chunk < NK) {
            uint32_t st = tiles + (uint32_t)(chunk % STAGES) * STAGE_BYTES;
            const size_t gofs = (size_t)chunk * BK + cc * 8;
            uint32_t sw = (uint32_t)((cc ^ ((lr >> 1) & 3)) << 4);
            uint32_t rowb = (uint32_t)lr * 64u;
            cp16(st + rowb + sw,              Ah + arow + (size_t)lr * KDIM + gofs);
            cp16(st + APLANE + rowb + sw,     Al + arow + (size_t)lr * KDIM + gofs);
            cp16(st + 2 * APLANE + rowb + sw, Bh + brow + (size_t)lr * KDIM + gofs);
            int r2 = lr + 64;
            uint32_t sw2 = (uint32_t)((cc ^ ((r2 >> 1) & 3)) << 4);
            uint32_t rowb2 = (uint32_t)r2 * 64u;
            cp16(st + 2 * APLANE + rowb2 + sw2, Bh + brow + (size_t)r2 * KDIM + gofs);
        }
        cp_commit();
    };

#pragma unroll
    for (int c0 = 0; c0 < STAGES - 1; c0++) load_chunk(c0);

    // ldmatrix lane->row/chunk mapping (m16n8k16 fragment layouts)
    const int aR = warp_m * 32 + (lane & 7) + ((lane >> 3) & 1) * 8;
    const int aC = lane >> 4;
    const int bR = warp_n * 32 + (lane & 7) + ((lane >> 4) << 3);
    const int bC = (lane >> 3) & 1;

    // double-buffered fragments
    uint32_t ahf[2][2][4], alf[2][2][4], bhf[2][4][2];

    auto ldfrags = [&](int buf, uint32_t st, int ks) {
#pragma unroll
        for (int tm = 0; tm < 2; tm++) {
            int row = aR + tm * 16;
            uint32_t cidx = (uint32_t)((ks * 2 + aC) ^ ((row >> 1) & 3));
            uint32_t ad = st + (uint32_t)row * 64u + (cidx << 4);
            LDM4(ahf[buf][tm][0], ahf[buf][tm][1], ahf[buf][tm][2], ahf[buf][tm][3], ad);
            LDM4(alf[buf][tm][0], alf[buf][tm][1], alf[buf][tm][2], alf[buf][tm][3], ad + APLANE);
        }
#pragma unroll
        for (int p = 0; p < 2; p++) {
            int row = bR + p * 16;
            uint32_t cidx = (uint32_t)((ks * 2 + bC) ^ ((row >> 1) & 3));
            uint32_t bd = st + 2 * APLANE + (uint32_t)row * 64u + (cidx << 4);
            uint32_t r0, r1, r2, r3;
            LDM4(r0, r1, r2, r3, bd);
            bhf[buf][2 * p][0] = r0; bhf[buf][2 * p][1] = r1;
            bhf[buf][2 * p + 1][0] = r2; bhf[buf][2 * p + 1][1] = r3;
        }
    };

    auto mma_pass = [&](int buf) {
#pragma unroll
        for (int tm = 0; tm < 2; tm++)
#pragma unroll
            for (int tn = 0; tn < 4; tn++)
                MMA(c[tm][tn], ahf[buf][tm], bhf[buf][tn][0], bhf[buf][tn][1]);   // Ah*Bh
#pragma unroll
        for (int tm = 0; tm < 2; tm++)
#pragma unroll
            for (int tn = 0; tn < 4; tn++)
                MMA(c[tm][tn], alf[buf][tm], bhf[buf][tn][0], bhf[buf][tn][1]);   // Al*Bh
    };

    cp_wait2();             // chunk 0 arrived (3 groups committed, <=2 pending)
    __syncthreads();
    ldfrags(0, tiles, 0);   // chunk 0, ks=0

#pragma unroll 1
    for (int k = 0; k < NK; k++) {
        uint32_t st = tiles + (uint32_t)(k % STAGES) * STAGE_BYTES;
        ldfrags(1, st, 1);              // ks=1 frags: overlaps with buf0 MMAs below
        mma_pass(0);
        cp_wait1();                     // chunk k+1 arrived
        __syncthreads();                // all warps done reading chunk k-1 stage
        load_chunk(k + STAGES - 1);     // refill stage (k-1)%4 with chunk k+3
        if (k + 1 < NK) {
            uint32_t st2 = tiles + (uint32_t)((k + 1) % STAGES) * STAGE_BYTES;
            ldfrags(0, st2, 0);         // prefetch next chunk ks=0: overlaps buf1 MMAs
        }
        mma_pass(1);
    }

    // ---- epilogue ----
    int r0 = mtile * BM + warp_m * 32 + (lane >> 2);
    int col0 = ntile * BN + warp_n * 32 + (lane & 3) * 2;
#pragma unroll
    for (int tm = 0; tm < 2; tm++)
#pragma unroll
        for (int tn = 0; tn < 4; tn++) {
            int r = r0 + tm * 16, ccc = col0 + tn * 8;
            float* v = c[tm][tn];
            if (PACK) {
                // B-side output: single fp16 plane (consistent with 2-product model)
#pragma unroll
                for (int h = 0; h < 2; h++) {
                    size_t off = (size_t)(r + h * 8) * KDIM + ccc;
                    *(__half2*)(Oh + off) =
                        __halves2half2(__float2half_rn(v[2 * h]), __float2half_rn(v[2 * h + 1]));
                }
            } else {
                *(float2*)(out + (size_t)r * KDIM + ccc) = make_float2(v[0], v[1]);
                *(float2*)(out + (size_t)(r + 8) * KDIM + ccc) = make_float2(v[2], v[3]);
            }
        }
}

// ---------------- launch ----------------
// out = X * (W0*W1*W2):
//   P1 = W0 * W1                 (A = W0 hi+lo,  B = fp16(W1^T))
//   Q  = (P1*W2)^T  via  Q[j][k2] = sum_t W2^T[j][t] * P1[k2][t]   (A = W2^T hi+lo, B = fp16(P1))
//   out = X * Wc    via  out[i][j] = sum_k2 X[i][k2] * Q[j][k2]    (A = X hi+lo,    B = fp16(Q))
extern "C" void kernel_launch(void* const* d_in, const int* in_sizes, int n_in,
                              void* d_out, int out_size) {
    const float* x0 = (const float*)d_in[0];
    const float* x1 = (const float*)d_in[1];
    const float* W0 = (const float*)d_in[2];
    const float* W1 = (const float*)d_in[3];
    const float* W2 = (const float*)d_in[4];
    float* out = (float*)d_out;

    cudaFuncSetAttribute(gemm_kernel<true, 5>,
                         cudaFuncAttributeMaxDynamicSharedMemorySize, SMEM_DYN);
    cudaFuncSetAttribute(gemm_kernel<false, 6>,
                         cudaFuncAttributeMaxDynamicSharedMemorySize, SMEM_DYN);

    pack_x_kernel<<<8192, 256>>>(x0, x1);
    pack_rm_kernel<<<4096, 256>>>(W0, OFF_A0);
    pack_wt_kernel<false><<<dim3(64, 64), dim3(32, 8)>>>(W1, OFF_B1);
    pack_wt_kernel<true ><<<dim3(64, 64), dim3(32, 8)>>>(W2, OFF_A2);

    gemm_kernel<true, 5><<<32 * 16, 256, SMEM_DYN>>>(OFF_A0, OFF_B1, OFF_P1, nullptr);
    gemm_kernel<true, 5><<<32 * 16, 256, SMEM_DYN>>>(OFF_A2, OFF_P1, OFF_Q, nullptr);
    gemm_kernel<false, 6><<<64 * 16, 256, SMEM_DYN>>>(OFF_X, OFF_Q, 0, out);
}

// round 10
// speedup vs baseline: 3.3715x; 1.2304x over previous
#include <cuda_runtime.h>
#include <cuda_fp16.h>
#include <cstdint>
#include <cstddef>

#define DI __device__ __forceinline__

// ---------------- problem constants ----------------
constexpr int KDIM  = 2048;           // K == N for every GEMM
constexpr int BM = 64, BN = 128, BK = 32;
constexpr int NK = KDIM / BK;         // 64 k-chunks
constexpr int STAGES = 4;
constexpr uint32_t APLANE = BM * 64u;                 // 4096 B
constexpr uint32_t BPLANE = BN * 64u;                 // 8192 B
// stage bytes: NPROD*APLANE + BPLANE (computed inline; no constexpr fn for device use)
constexpr uint32_t SMEM_DYN1 = STAGES * (1 * APLANE + BPLANE) + 128;   // 1-product
constexpr uint32_t SMEM_DYN2 = STAGES * (2 * APLANE + BPLANE) + 128;   // 2-product

// ---------------- plane pool ----------------
// X keeps hi+lo planes (A-side of the accurate final GEMM).
// All weight-path tensors are single fp16 (hi plane only).
constexpr size_t MEG = 1024ull * 1024ull;
constexpr size_t OFF_X  = 0;          // X = concat(x0,x1)   [4096 x 2048]  hi+lo
constexpr size_t OFF_A0 = 8 * MEG;    // fp16(W0) row-major  [2048 x 2048]  hi
constexpr size_t OFF_B1 = 12 * MEG;   // fp16(W1^T)          [2048 x 2048]  hi
constexpr size_t OFF_A2 = 16 * MEG;   // fp16(W2^T)          [2048 x 2048]  hi
constexpr size_t OFF_P1 = 20 * MEG;   // P1 = W0*W1          [2048 x 2048]  hi
constexpr size_t OFF_Q  = 24 * MEG;   // Q  = (W0*W1*W2)^T   [2048 x 2048]  hi
constexpr size_t POOL   = 28 * MEG;

__device__ __half g_H[POOL];          // hi planes
__device__ __half g_L[POOL];          // lo planes (X only)

// ---------------- helpers ----------------
DI uint32_t s2u(const void* p) {
    uint32_t r;
    asm("{ .reg .u64 t; cvta.to.shared.u64 t, %1; cvt.u32.u64 %0, t; }" : "=r"(r) : "l"(p));
    return r;
}
DI void cp16(uint32_t dst, const void* src) {
    asm volatile(
        "{ .reg .u64 g; cvta.to.global.u64 g, %1; cp.async.cg.shared.global [%0], [g], 16; }"
        :: "r"(dst), "l"(src) : "memory");
}
DI void cp_commit() { asm volatile("cp.async.commit_group;" ::: "memory"); }
DI void cp_wait1()  { asm volatile("cp.async.wait_group 1;" ::: "memory"); }
DI void cp_wait2()  { asm volatile("cp.async.wait_group 2;" ::: "memory"); }

#define LDM4(R0, R1, R2, R3, ADDR) \
    asm volatile("ldmatrix.sync.aligned.m8n8.x4.shared.b16 {%0,%1,%2,%3}, [%4];" \
                 : "=r"(R0), "=r"(R1), "=r"(R2), "=r"(R3) : "r"(ADDR))

#define MMA(C, A, B0, B1) \
    asm volatile("mma.sync.aligned.m16n8k16.row.col.f32.f16.f16.f32 " \
                 "{%0,%1,%2,%3},{%4,%5,%6,%7},{%8,%9},{%0,%1,%2,%3};" \
                 : "+f"((C)[0]), "+f"((C)[1]), "+f"((C)[2]), "+f"((C)[3]) \
                 : "r"((A)[0]), "r"((A)[1]), "r"((A)[2]), "r"((A)[3]), "r"(B0), "r"(B1))

DI void split1(float f, __half& h, __half& l) {
    h = __float2half_rn(f);
    l = __float2half_rn(f - __half2float(h));
}

// ============ prologue: pack concat(x0,x1) -> hi+lo planes @ OFF_X ============
__global__ void pack_x_kernel(const float* __restrict__ x0, const float* __restrict__ x1) {
    int id = blockIdx.x * 256 + threadIdx.x;       // 2M threads, one float4 each
    int m = id >> 9;
    int c4 = (id & 511) * 4;
    const float* s = (c4 < 1024) ? (x0 + (size_t)m * 1024 + c4)
                                 : (x1 + (size_t)m * 1024 + (c4 - 1024));
    float4 v = *(const float4*)s;
    __half h0, h1, h2, h3, l0, l1, l2, l3;
    split1(v.x, h0, l0); split1(v.y, h1, l1);
    split1(v.z, h2, l2); split1(v.w, h3, l3);
    size_t off = OFF_X + (size_t)m * KDIM + c4;
    *(__half2*)(&g_H[off])     = __halves2half2(h0, h1);
    *(__half2*)(&g_H[off + 2]) = __halves2half2(h2, h3);
    *(__half2*)(&g_L[off])     = __halves2half2(l0, l1);
    *(__half2*)(&g_L[off + 2]) = __halves2half2(l2, l3);
}

// ============ prologue: row-major fp16 pack (W0) @ dstoff ============
__global__ void pack_rm_kernel(const float* __restrict__ src, size_t dstoff) {
    int id = blockIdx.x * 256 + threadIdx.x;       // 1M threads (2048x2048/4)
    int m = id >> 9;
    int c4 = (id & 511) * 4;
    float4 v = *(const float4*)(src + (size_t)m * KDIM + c4);
    size_t off = dstoff + (size_t)m * KDIM + c4;
    *(__half2*)(&g_H[off])     = __halves2half2(__float2half_rn(v.x), __float2half_rn(v.y));
    *(__half2*)(&g_H[off + 2]) = __halves2half2(__float2half_rn(v.z), __float2half_rn(v.w));
}

// ============ prologue: transposed fp16 pack (W^T) @ dstoff ============
__global__ void pack_wt_kernel(const float* __restrict__ W, size_t dstoff) {
    __shared__ float s[32][33];
    int n0 = blockIdx.x * 32, k0 = blockIdx.y * 32;
    int tx = threadIdx.x, ty = threadIdx.y;  // (32, 8)
#pragma unroll
    for (int i = 0; i < 4; i++)
        s[ty + i * 8][tx] = W[(size_t)(k0 + ty + i * 8) * KDIM + n0 + tx];
    __syncthreads();
#pragma unroll
    for (int i = 0; i < 4; i++) {
        float v = s[tx][ty + i * 8];           // (k_local=tx, n_local=ty+8i)
        size_t off = dstoff + (size_t)(n0 + ty + i * 8) * KDIM + k0 + tx;
        g_H[off] = __float2half_rn(v);
    }
}

// ============ main GEMM ============
// NPROD==2: C = (Ah+Al) @ Bh^T  (split-fp16 A, fp16 B)
// NPROD==1: C = Ah @ Bh^T       (plain fp16 GEMM)
template <bool PACK, int MSHIFT, int NPROD>
__global__ void __launch_bounds__(256, 2)
gemm_kernel(size_t aoff, size_t boff, size_t ooff, float* __restrict__ out) {
    constexpr uint32_t SB = (uint32_t)NPROD * APLANE + BPLANE;  // stage bytes
    constexpr uint32_t BOFF = (uint32_t)NPROD * APLANE;         // B plane offset in stage
    extern __shared__ uint8_t smem[];
    uint32_t tiles = (s2u(smem) + 127u) & ~127u;

    const __half* Ah = g_H + aoff;
    const __half* Al = g_L + aoff;
    const __half* Bh = g_H + boff;
    __half* Oh = g_H + ooff;

    int tid = threadIdx.x, lane = tid & 31, wid = tid >> 5;
    int warp_m = wid >> 2, warp_n = wid & 3;            // 2 x 4 warp grid, 32x32 tiles
    int mtile = blockIdx.x & ((1 << MSHIFT) - 1), ntile = blockIdx.x >> MSHIFT;

    const size_t arow = (size_t)mtile * BM * KDIM;
    const size_t brow = (size_t)ntile * BN * KDIM;

    float c[2][4][4];
#pragma unroll
    for (int a = 0; a < 2; a++)
#pragma unroll
        for (int b = 0; b < 4; b++)
#pragma unroll
            for (int d = 0; d < 4; d++) c[a][b][d] = 0.f;

    // per-chunk loader: A planes (64 rows each) + Bh (128 rows), 64B/row, swizzled
    const int lr = tid >> 2;         // 0..63
    const int cc = tid & 3;
    auto load_chunk = [&](int chunk) {
        if (chunk < NK) {
            uint32_t st = tiles + (uint32_t)(chunk % STAGES) * SB;
            const size_t gofs = (size_t)chunk * BK + cc * 8;
            uint32_t sw = (uint32_t)((cc ^ ((lr >> 1) & 3)) << 4);
            uint32_t rowb = (uint32_t)lr * 64u;
            cp16(st + rowb + sw, Ah + arow + (size_t)lr * KDIM + gofs);
            if (NPROD == 2)
                cp16(st + APLANE + rowb + sw, Al + arow + (size_t)lr * KDIM + gofs);
            cp16(st + BOFF + rowb + sw, Bh + brow + (size_t)lr * KDIM + gofs);
            int r2 = lr + 64;
            uint32_t sw2 = (uint32_t)((cc ^ ((r2 >> 1) & 3)) << 4);
            uint32_t rowb2 = (uint32_t)r2 * 64u;
            cp16(st + BOFF + rowb2 + sw2, Bh + brow + (size_t)r2 * KDIM + gofs);
        }
        cp_commit();
    };

#pragma unroll
    for (int c0 = 0; c0 < STAGES - 1; c0++) load_chunk(c0);

    // ldmatrix lane->row/chunk mapping (m16n8k16 fragment layouts)
    const int aR = warp_m * 32 + (lane & 7) + ((lane >> 3) & 1) * 8;
    const int aC = lane >> 4;
    const int bR = warp_n * 32 + (lane & 7) + ((lane >> 4) << 3);
    const int bC = (lane >> 3) & 1;

    // double-buffered fragments
    uint32_t ahf[2][2][4], alf[2][2][4], bhf[2][4][2];

    auto ldfrags = [&](int buf, uint32_t st, int ks) {
#pragma unroll
        for (int tm = 0; tm < 2; tm++) {
            int row = aR + tm * 16;
            uint32_t cidx = (uint32_t)((ks * 2 + aC) ^ ((row >> 1) & 3));
            uint32_t ad = st + (uint32_t)row * 64u + (cidx << 4);
            LDM4(ahf[buf][tm][0], ahf[buf][tm][1], ahf[buf][tm][2], ahf[buf][tm][3], ad);
            if (NPROD == 2)
                LDM4(alf[buf][tm][0], alf[buf][tm][1], alf[buf][tm][2], alf[buf][tm][3],
                     ad + APLANE);
        }
#pragma unroll
        for (int p = 0; p < 2; p++) {
            int row = bR + p * 16;
            uint32_t cidx = (uint32_t)((ks * 2 + bC) ^ ((row >> 1) & 3));
            uint32_t bd = st + BOFF + (uint32_t)row * 64u + (cidx << 4);
            uint32_t r0, r1, r2, r3;
            LDM4(r0, r1, r2, r3, bd);
            bhf[buf][2 * p][0] = r0; bhf[buf][2 * p][1] = r1;
            bhf[buf][2 * p + 1][0] = r2; bhf[buf][2 * p + 1][1] = r3;
        }
    };

    auto mma_pass = [&](int buf) {
#pragma unroll
        for (int tm = 0; tm < 2; tm++)
#pragma unroll
            for (int tn = 0; tn < 4; tn++)
                MMA(c[tm][tn], ahf[buf][tm], bhf[buf][tn][0], bhf[buf][tn][1]);   // Ah*Bh
        if (NPROD == 2) {
#pragma unroll
            for (int tm = 0; tm < 2; tm++)
#pragma unroll
                for (int tn = 0; tn < 4; tn++)
                    MMA(c[tm][tn], alf[buf][tm], bhf[buf][tn][0], bhf[buf][tn][1]); // Al*Bh
        }
    };

    cp_wait2();             // chunk 0 arrived (3 groups committed, <=2 pending)
    __syncthreads();
    ldfrags(0, tiles, 0);   // chunk 0, ks=0

#pragma unroll 1
    for (int k = 0; k < NK; k++) {
        uint32_t st = tiles + (uint32_t)(k % STAGES) * SB;
        ldfrags(1, st, 1);              // ks=1 frags: overlaps with buf0 MMAs below
        mma_pass(0);
        cp_wait1();                     // chunk k+1 arrived
        __syncthreads();                // all warps done reading chunk k-1 stage
        load_chunk(k + STAGES - 1);     // refill stage (k-1)%4 with chunk k+3
        if (k + 1 < NK) {
            uint32_t st2 = tiles + (uint32_t)((k + 1) % STAGES) * SB;
            ldfrags(0, st2, 0);         // prefetch next chunk ks=0: overlaps buf1 MMAs
        }
        mma_pass(1);
    }

    // ---- epilogue ----
    int r0 = mtile * BM + warp_m * 32 + (lane >> 2);
    int col0 = ntile * BN + warp_n * 32 + (lane & 3) * 2;
#pragma unroll
    for (int tm = 0; tm < 2; tm++)
#pragma unroll
        for (int tn = 0; tn < 4; tn++) {
            int r = r0 + tm * 16, ccc = col0 + tn * 8;
            float* v = c[tm][tn];
            if (PACK) {
                // downstream consumers read a single fp16 plane
#pragma unroll
                for (int h = 0; h < 2; h++) {
                    size_t off = (size_t)(r + h * 8) * KDIM + ccc;
                    *(__half2*)(Oh + off) =
                        __halves2half2(__float2half_rn(v[2 * h]), __float2half_rn(v[2 * h + 1]));
                }
            } else {
                *(float2*)(out + (size_t)r * KDIM + ccc) = make_float2(v[0], v[1]);
                *(float2*)(out + (size_t)(r + 8) * KDIM + ccc) = make_float2(v[2], v[3]);
            }
        }
}

// ---------------- launch ----------------
// out = X * (W0*W1*W2):
//   P1 = fp16(W0) * fp16(W1^T)^T                       1-product GEMM
//   Q  = (P1*W2)^T : Q[j][t2] = sum_t W2^T[j][t]*P1[t2][t]   1-product GEMM
//   out[i][j] = sum_k X[i][k]*Q[j][k]                  2-product GEMM (X hi+lo)
extern "C" void kernel_launch(void* const* d_in, const int* in_sizes, int n_in,
                              void* d_out, int out_size) {
    const float* x0 = (const float*)d_in[0];
    const float* x1 = (const float*)d_in[1];
    const float* W0 = (const float*)d_in[2];
    const float* W1 = (const float*)d_in[3];
    const float* W2 = (const float*)d_in[4];
    float* out = (float*)d_out;

    cudaFuncSetAttribute(gemm_kernel<true, 5, 1>,
                         cudaFuncAttributeMaxDynamicSharedMemorySize, SMEM_DYN1);
    cudaFuncSetAttribute(gemm_kernel<false, 6, 2>,
                         cudaFuncAttributeMaxDynamicSharedMemorySize, SMEM_DYN2);

    pack_x_kernel<<<8192, 256>>>(x0, x1);
    pack_rm_kernel<<<4096, 256>>>(W0, OFF_A0);
    pack_wt_kernel<<<dim3(64, 64), dim3(32, 8)>>>(W1, OFF_B1);
    pack_wt_kernel<<<dim3(64, 64), dim3(32, 8)>>>(W2, OFF_A2);

    gemm_kernel<true, 5, 1><<<32 * 16, 256, SMEM_DYN1>>>(OFF_A0, OFF_B1, OFF_P1, nullptr);
    gemm_kernel<true, 5, 1><<<32 * 16, 256, SMEM_DYN1>>>(OFF_A2, OFF_P1, OFF_Q, nullptr);
    gemm_kernel<false, 6, 2><<<64 * 16, 256, SMEM_DYN2>>>(OFF_X, OFF_Q, 0, out);
}

// round 11
// speedup vs baseline: 4.2094x; 1.2485x over previous
#include <cuda_runtime.h>
#include <cuda_fp16.h>
#include <cstdint>
#include <cstddef>

#define DI __device__ __forceinline__

// ---------------- problem constants ----------------
constexpr int KDIM  = 2048;           // K == N for every GEMM
constexpr int BM = 64, BN = 128, BK = 32;
constexpr int NK = KDIM / BK;         // 64 k-chunks
constexpr int STAGES = 4;
constexpr uint32_t APLANE = BM * 64u;                 // 4096 B
constexpr uint32_t BPLANE = BN * 64u;                 // 8192 B
constexpr uint32_t SMEM_DYN1 = STAGES * (1 * APLANE + BPLANE) + 128;   // 1-product

// ---------------- plane pool (all tensors single fp16 plane) ----------------
constexpr size_t MEG = 1024ull * 1024ull;
constexpr size_t OFF_X  = 0;          // fp16(concat(x0,x1)) [4096 x 2048]
constexpr size_t OFF_A0 = 8 * MEG;    // fp16(W0) row-major  [2048 x 2048]
constexpr size_t OFF_B1 = 12 * MEG;   // fp16(W1^T)          [2048 x 2048]
constexpr size_t OFF_A2 = 16 * MEG;   // fp16(W2^T)          [2048 x 2048]
constexpr size_t OFF_P1 = 20 * MEG;   // P1 = W0*W1          [2048 x 2048]
constexpr size_t OFF_Q  = 24 * MEG;   // Q  = (W0*W1*W2)^T   [2048 x 2048]
constexpr size_t POOL   = 28 * MEG;

__device__ __half g_H[POOL];          // fp16 planes
__device__ __half g_L[POOL];          // lo planes (unused in 1-product mode; kept for fallback)

// ---------------- helpers ----------------
DI uint32_t s2u(const void* p) {
    uint32_t r;
    asm("{ .reg .u64 t; cvta.to.shared.u64 t, %1; cvt.u32.u64 %0, t; }" : "=r"(r) : "l"(p));
    return r;
}
DI void cp16(uint32_t dst, const void* src) {
    asm volatile(
        "{ .reg .u64 g; cvta.to.global.u64 g, %1; cp.async.cg.shared.global [%0], [g], 16; }"
        :: "r"(dst), "l"(src) : "memory");
}
DI void cp_commit() { asm volatile("cp.async.commit_group;" ::: "memory"); }
DI void cp_wait1()  { asm volatile("cp.async.wait_group 1;" ::: "memory"); }
DI void cp_wait2()  { asm volatile("cp.async.wait_group 2;" ::: "memory"); }

#define LDM4(R0, R1, R2, R3, ADDR) \
    asm volatile("ldmatrix.sync.aligned.m8n8.x4.shared.b16 {%0,%1,%2,%3}, [%4];" \
                 : "=r"(R0), "=r"(R1), "=r"(R2), "=r"(R3) : "r"(ADDR))

#define MMA(C, A, B0, B1) \
    asm volatile("mma.sync.aligned.m16n8k16.row.col.f32.f16.f16.f32 " \
                 "{%0,%1,%2,%3},{%4,%5,%6,%7},{%8,%9},{%0,%1,%2,%3};" \
                 : "+f"((C)[0]), "+f"((C)[1]), "+f"((C)[2]), "+f"((C)[3]) \
                 : "r"((A)[0]), "r"((A)[1]), "r"((A)[2]), "r"((A)[3]), "r"(B0), "r"(B1))

// ============ prologue: pack concat(x0,x1) -> fp16 plane @ OFF_X ============
__global__ void pack_x_kernel(const float* __restrict__ x0, const float* __restrict__ x1) {
    int id = blockIdx.x * 256 + threadIdx.x;       // 2M threads, one float4 each
    int m = id >> 9;
    int c4 = (id & 511) * 4;
    const float* s = (c4 < 1024) ? (x0 + (size_t)m * 1024 + c4)
                                 : (x1 + (size_t)m * 1024 + (c4 - 1024));
    float4 v = *(const float4*)s;
    size_t off = OFF_X + (size_t)m * KDIM + c4;
    *(__half2*)(&g_H[off])     = __halves2half2(__float2half_rn(v.x), __float2half_rn(v.y));
    *(__half2*)(&g_H[off + 2]) = __halves2half2(__float2half_rn(v.z), __float2half_rn(v.w));
}

// ============ prologue: row-major fp16 pack (W0) @ dstoff ============
__global__ void pack_rm_kernel(const float* __restrict__ src, size_t dstoff) {
    int id = blockIdx.x * 256 + threadIdx.x;       // 1M threads (2048x2048/4)
    int m = id >> 9;
    int c4 = (id & 511) * 4;
    float4 v = *(const float4*)(src + (size_t)m * KDIM + c4);
    size_t off = dstoff + (size_t)m * KDIM + c4;
    *(__half2*)(&g_H[off])     = __halves2half2(__float2half_rn(v.x), __float2half_rn(v.y));
    *(__half2*)(&g_H[off + 2]) = __halves2half2(__float2half_rn(v.z), __float2half_rn(v.w));
}

// ============ prologue: transposed fp16 pack (W^T) @ dstoff ============
__global__ void pack_wt_kernel(const float* __restrict__ W, size_t dstoff) {
    __shared__ float s[32][33];
    int n0 = blockIdx.x * 32, k0 = blockIdx.y * 32;
    int tx = threadIdx.x, ty = threadIdx.y;  // (32, 8)
#pragma unroll
    for (int i = 0; i < 4; i++)
        s[ty + i * 8][tx] = W[(size_t)(k0 + ty + i * 8) * KDIM + n0 + tx];
    __syncthreads();
#pragma unroll
    for (int i = 0; i < 4; i++) {
        float v = s[tx][ty + i * 8];           // (k_local=tx, n_local=ty+8i)
        size_t off = dstoff + (size_t)(n0 + ty + i * 8) * KDIM + k0 + tx;
        g_H[off] = __float2half_rn(v);
    }
}

// ============ main GEMM: C = Ah @ Bh^T (plain fp16, fp32 accumulate) ============
template <bool PACK, int MSHIFT, int NPROD>
__global__ void __launch_bounds__(256, 2)
gemm_kernel(size_t aoff, size_t boff, size_t ooff, float* __restrict__ out) {
    constexpr uint32_t SB = (uint32_t)NPROD * APLANE + BPLANE;  // stage bytes
    constexpr uint32_t BOFF = (uint32_t)NPROD * APLANE;         // B plane offset in stage
    extern __shared__ uint8_t smem[];
    uint32_t tiles = (s2u(smem) + 127u) & ~127u;

    const __half* Ah = g_H + aoff;
    const __half* Al = g_L + aoff;
    const __half* Bh = g_H + boff;
    __half* Oh = g_H + ooff;

    int tid = threadIdx.x, lane = tid & 31, wid = tid >> 5;
    int warp_m = wid >> 2, warp_n = wid & 3;            // 2 x 4 warp grid, 32x32 tiles
    int mtile = blockIdx.x & ((1 << MSHIFT) - 1), ntile = blockIdx.x >> MSHIFT;

    const size_t arow = (size_t)mtile * BM * KDIM;
    const size_t brow = (size_t)ntile * BN * KDIM;

    float c[2][4][4];
#pragma unroll
    for (int a = 0; a < 2; a++)
#pragma unroll
        for (int b = 0; b < 4; b++)
#pragma unroll
            for (int d = 0; d < 4; d++) c[a][b][d] = 0.f;

    // per-chunk loader: A planes (64 rows each) + Bh (128 rows), 64B/row, swizzled
    const int lr = tid >> 2;         // 0..63
    const int cc = tid & 3;
    auto load_chunk = [&](int chunk) {
        if (chunk < NK) {
            uint32_t st = tiles + (uint32_t)(chunk % STAGES) * SB;
            const size_t gofs = (size_t)chunk * BK + cc * 8;
            uint32_t sw = (uint32_t)((cc ^ ((lr >> 1) & 3)) << 4);
            uint32_t rowb = (uint32_t)lr * 64u;
            cp16(st + rowb + sw, Ah + arow + (size_t)lr * KDIM + gofs);
            if (NPROD == 2)
                cp16(st + APLANE + rowb + sw, Al + arow + (size_t)lr * KDIM + gofs);
            cp16(st + BOFF + rowb + sw, Bh + brow + (size_t)lr * KDIM + gofs);
            int r2 = lr + 64;
            uint32_t sw2 = (uint32_t)((cc ^ ((r2 >> 1) & 3)) << 4);
            uint32_t rowb2 = (uint32_t)r2 * 64u;
            cp16(st + BOFF + rowb2 + sw2, Bh + brow + (size_t)r2 * KDIM + gofs);
        }
        cp_commit();
    };

#pragma unroll
    for (int c0 = 0; c0 < STAGES - 1; c0++) load_chunk(c0);

    // ldmatrix lane->row/chunk mapping (m16n8k16 fragment layouts)
    const int aR = warp_m * 32 + (lane & 7) + ((lane >> 3) & 1) * 8;
    const int aC = lane >> 4;
    const int bR = warp_n * 32 + (lane & 7) + ((lane >> 4) << 3);
    const int bC = (lane >> 3) & 1;

    // double-buffered fragments
    uint32_t ahf[2][2][4], alf[2][2][4], bhf[2][4][2];

    auto ldfrags = [&](int buf, uint32_t st, int ks) {
#pragma unroll
        for (int tm = 0; tm < 2; tm++) {
            int row = aR + tm * 16;
            uint32_t cidx = (uint32_t)((ks * 2 + aC) ^ ((row >> 1) & 3));
            uint32_t ad = st + (uint32_t)row * 64u + (cidx << 4);
            LDM4(ahf[buf][tm][0], ahf[buf][tm][1], ahf[buf][tm][2], ahf[buf][tm][3], ad);
            if (NPROD == 2)
                LDM4(alf[buf][tm][0], alf[buf][tm][1], alf[buf][tm][2], alf[buf][tm][3],
                     ad + APLANE);
        }
#pragma unroll
        for (int p = 0; p < 2; p++) {
            int row = bR + p * 16;
            uint32_t cidx = (uint32_t)((ks * 2 + bC) ^ ((row >> 1) & 3));
            uint32_t bd = st + BOFF + (uint32_t)row * 64u + (cidx << 4);
            uint32_t r0, r1, r2, r3;
            LDM4(r0, r1, r2, r3, bd);
            bhf[buf][2 * p][0] = r0; bhf[buf][2 * p][1] = r1;
            bhf[buf][2 * p + 1][0] = r2; bhf[buf][2 * p + 1][1] = r3;
        }
    };

    auto mma_pass = [&](int buf) {
#pragma unroll
        for (int tm = 0; tm < 2; tm++)
#pragma unroll
            for (int tn = 0; tn < 4; tn++)
                MMA(c[tm][tn], ahf[buf][tm], bhf[buf][tn][0], bhf[buf][tn][1]);   // Ah*Bh
        if (NPROD == 2) {
#pragma unroll
            for (int tm = 0; tm < 2; tm++)
#pragma unroll
                for (int tn = 0; tn < 4; tn++)
                    MMA(c[tm][tn], alf[buf][tm], bhf[buf][tn][0], bhf[buf][tn][1]); // Al*Bh
        }
    };

    cp_wait2();             // chunk 0 arrived (3 groups committed, <=2 pending)
    __syncthreads();
    ldfrags(0, tiles, 0);   // chunk 0, ks=0

#pragma unroll 1
    for (int k = 0; k < NK; k++) {
        uint32_t st = tiles + (uint32_t)(k % STAGES) * SB;
        ldfrags(1, st, 1);              // ks=1 frags: overlaps with buf0 MMAs below
        mma_pass(0);
        cp_wait1();                     // chunk k+1 arrived
        __syncthreads();                // all warps done reading chunk k-1 stage
        load_chunk(k + STAGES - 1);     // refill stage (k-1)%4 with chunk k+3
        if (k + 1 < NK) {
            uint32_t st2 = tiles + (uint32_t)((k + 1) % STAGES) * SB;
            ldfrags(0, st2, 0);         // prefetch next chunk ks=0: overlaps buf1 MMAs
        }
        mma_pass(1);
    }

    // ---- epilogue ----
    int r0 = mtile * BM + warp_m * 32 + (lane >> 2);
    int col0 = ntile * BN + warp_n * 32 + (lane & 3) * 2;
#pragma unroll
    for (int tm = 0; tm < 2; tm++)
#pragma unroll
        for (int tn = 0; tn < 4; tn++) {
            int r = r0 + tm * 16, ccc = col0 + tn * 8;
            float* v = c[tm][tn];
            if (PACK) {
                // downstream consumers read a single fp16 plane
#pragma unroll
                for (int h = 0; h < 2; h++) {
                    size_t off = (size_t)(r + h * 8) * KDIM + ccc;
                    *(__half2*)(Oh + off) =
                        __halves2half2(__float2half_rn(v[2 * h]), __float2half_rn(v[2 * h + 1]));
                }
            } else {
                *(float2*)(out + (size_t)r * KDIM + ccc) = make_float2(v[0], v[1]);
                *(float2*)(out + (size_t)(r + 8) * KDIM + ccc) = make_float2(v[2], v[3]);
            }
        }
}

// ---------------- launch ----------------
// out = X * (W0*W1*W2), all GEMMs plain fp16 with fp32 accumulate:
//   P1 = fp16(W0) * fp16(W1^T)^T
//   Q  = (P1*W2)^T : Q[j][t2] = sum_t W2^T[j][t]*P1[t2][t]
//   out[i][j] = sum_k fp16(X)[i][k]*Q[j][k]
extern "C" void kernel_launch(void* const* d_in, const int* in_sizes, int n_in,
                              void* d_out, int out_size) {
    const float* x0 = (const float*)d_in[0];
    const float* x1 = (const float*)d_in[1];
    const float* W0 = (const float*)d_in[2];
    const float* W1 = (const float*)d_in[3];
    const float* W2 = (const float*)d_in[4];
    float* out = (float*)d_out;

    cudaFuncSetAttribute(gemm_kernel<true, 5, 1>,
                         cudaFuncAttributeMaxDynamicSharedMemorySize, SMEM_DYN1);
    cudaFuncSetAttribute(gemm_kernel<false, 6, 1>,
                         cudaFuncAttributeMaxDynamicSharedMemorySize, SMEM_DYN1);

    pack_x_kernel<<<8192, 256>>>(x0, x1);
    pack_rm_kernel<<<4096, 256>>>(W0, OFF_A0);
    pack_wt_kernel<<<dim3(64, 64), dim3(32, 8)>>>(W1, OFF_B1);
    pack_wt_kernel<<<dim3(64, 64), dim3(32, 8)>>>(W2, OFF_A2);

    gemm_kernel<true, 5, 1><<<32 * 16, 256, SMEM_DYN1>>>(OFF_A0, OFF_B1, OFF_P1, nullptr);
    gemm_kernel<true, 5, 1><<<32 * 16, 256, SMEM_DYN1>>>(OFF_A2, OFF_P1, OFF_Q, nullptr);
    gemm_kernel<false, 6, 1><<<64 * 16, 256, SMEM_DYN1>>>(OFF_X, OFF_Q, 0, out);
}

// round 13
// speedup vs baseline: 4.2440x; 1.0082x over previous
#include <cuda_runtime.h>
#include <cuda_fp16.h>
#include <cstdint>
#include <cstddef>

#define DI __device__ __forceinline__

// ---------------- problem constants ----------------
constexpr int KDIM  = 2048;           // K == N for every GEMM
constexpr int BM = 64, BN = 128, BK = 32;
constexpr int NK = KDIM / BK;         // 64 k-chunks
constexpr int STAGES = 4;
constexpr uint32_t APLANE = BM * 64u;                 // 4096 B
constexpr uint32_t BPLANE = BN * 64u;                 // 8192 B
constexpr uint32_t STAGE_BYTES = APLANE + BPLANE;     // 12288
constexpr uint32_t SMEM_DYN = STAGES * STAGE_BYTES + 128;   // ~48KB -> 3 CTAs/SM

// ---------------- plane pool (all tensors single fp16 plane) ----------------
constexpr size_t MEG = 1024ull * 1024ull;
constexpr size_t OFF_X  = 0;          // fp16(concat(x0,x1)) [4096 x 2048]
constexpr size_t OFF_A0 = 8 * MEG;    // fp16(W0) row-major  [2048 x 2048]
constexpr size_t OFF_B1 = 12 * MEG;   // fp16(W1^T)          [2048 x 2048]
constexpr size_t OFF_A2 = 16 * MEG;   // fp16(W2^T)          [2048 x 2048]
constexpr size_t OFF_P1 = 20 * MEG;   // P1 = W0*W1          [2048 x 2048]
constexpr size_t OFF_Q  = 24 * MEG;   // Q  = (W0*W1*W2)^T   [2048 x 2048]
constexpr size_t POOL   = 28 * MEG;

__device__ __half g_H[POOL];          // fp16 planes

// ---------------- helpers ----------------
DI uint32_t s2u(const void* p) {
    uint32_t r;
    asm("{ .reg .u64 t; cvta.to.shared.u64 t, %1; cvt.u32.u64 %0, t; }" : "=r"(r) : "l"(p));
    return r;
}
DI void cp16(uint32_t dst, const void* src) {
    asm volatile(
        "{ .reg .u64 g; cvta.to.global.u64 g, %1; cp.async.cg.shared.global [%0], [g], 16; }"
        :: "r"(dst), "l"(src) : "memory");
}
DI void cp_commit() { asm volatile("cp.async.commit_group;" ::: "memory"); }
DI void cp_wait1()  { asm volatile("cp.async.wait_group 1;" ::: "memory"); }
DI void cp_wait2()  { asm volatile("cp.async.wait_group 2;" ::: "memory"); }

#define LDM4(R0, R1, R2, R3, ADDR) \
    asm volatile("ldmatrix.sync.aligned.m8n8.x4.shared.b16 {%0,%1,%2,%3}, [%4];" \
                 : "=r"(R0), "=r"(R1), "=r"(R2), "=r"(R3) : "r"(ADDR))

#define MMA(C, A, B0, B1) \
    asm volatile("mma.sync.aligned.m16n8k16.row.col.f32.f16.f16.f32 " \
                 "{%0,%1,%2,%3},{%4,%5,%6,%7},{%8,%9},{%0,%1,%2,%3};" \
                 : "+f"((C)[0]), "+f"((C)[1]), "+f"((C)[2]), "+f"((C)[3]) \
                 : "r"((A)[0]), "r"((A)[1]), "r"((A)[2]), "r"((A)[3]), "r"(B0), "r"(B1))

// ============ fused prologue: all packing in ONE kernel ============
// blocks [0, 8192)          : pack X = fp16(concat(x0,x1))        @ OFF_X
// blocks [8192, 12288)      : pack fp16(W0) row-major             @ OFF_A0
// blocks [12288, 16384)     : pack fp16(W1^T) (transpose)         @ OFF_B1
// blocks [16384, 20480)     : pack fp16(W2^T) (transpose)         @ OFF_A2
__global__ void pack_all_kernel(const float* __restrict__ x0, const float* __restrict__ x1,
                                const float* __restrict__ W0, const float* __restrict__ W1,
                                const float* __restrict__ W2) {
    __shared__ float s[32][33];
    int b = blockIdx.x, tid = threadIdx.x;
    if (b < 12288) {
        const float* src;
        size_t off;
        if (b < 8192) {
            int id = b * 256 + tid;
            int m = id >> 9;
            int c4 = (id & 511) * 4;
            src = (c4 < 1024) ? (x0 + (size_t)m * 1024 + c4)
                              : (x1 + (size_t)m * 1024 + (c4 - 1024));
            off = OFF_X + (size_t)m * KDIM + c4;
        } else {
            int id = (b - 8192) * 256 + tid;
            int m = id >> 9;
            int c4 = (id & 511) * 4;
            src = W0 + (size_t)m * KDIM + c4;
            off = OFF_A0 + (size_t)m * KDIM + c4;
        }
        float4 v = *(const float4*)src;
        *(__half2*)(&g_H[off])     = __halves2half2(__float2half_rn(v.x), __float2half_rn(v.y));
        *(__half2*)(&g_H[off + 2]) = __halves2half2(__float2half_rn(v.z), __float2half_rn(v.w));
    } else {
        const float* W = (b < 16384) ? W1 : W2;
        size_t dstoff = (b < 16384) ? OFF_B1 : OFF_A2;
        int bb = (b < 16384) ? (b - 12288) : (b - 16384);
        int n0 = (bb & 63) * 32, k0 = (bb >> 6) * 32;
        int tx = tid & 31, ty = tid >> 5;     // (32, 8)
#pragma unroll
        for (int i = 0; i < 4; i++)
            s[ty + i * 8][tx] = W[(size_t)(k0 + ty + i * 8) * KDIM + n0 + tx];
        __syncthreads();
#pragma unroll
        for (int i = 0; i < 4; i++) {
            float v = s[tx][ty + i * 8];      // (k_local=tx, n_local=ty+8i)
            size_t off = dstoff + (size_t)(n0 + ty + i * 8) * KDIM + k0 + tx;
            g_H[off] = __float2half_rn(v);
        }
    }
}

// ============ main GEMM: C = Ah @ Bh^T (plain fp16, fp32 accumulate) ============
template <bool PACK, int MSHIFT>
__global__ void __launch_bounds__(256, 3)
gemm_kernel(size_t aoff, size_t boff, size_t ooff, float* __restrict__ out) {
    extern __shared__ uint8_t smem[];
    uint32_t tiles = (s2u(smem) + 127u) & ~127u;

    const __half* Ah = g_H + aoff;
    const __half* Bh = g_H + boff;
    __half* Oh = g_H + ooff;

    int tid = threadIdx.x, lane = tid & 31, wid = tid >> 5;
    int warp_m = wid >> 2, warp_n = wid & 3;            // 2 x 4 warp grid, 32x32 tiles
    int mtile = blockIdx.x & ((1 << MSHIFT) - 1), ntile = blockIdx.x >> MSHIFT;

    const size_t arow = (size_t)mtile * BM * KDIM;
    const size_t brow = (size_t)ntile * BN * KDIM;

    float c[2][4][4];
#pragma unroll
    for (int a = 0; a < 2; a++)
#pragma unroll
        for (int b = 0; b < 4; b++)
#pragma unroll
            for (int d = 0; d < 4; d++) c[a][b][d] = 0.f;

    // per-chunk loader: A (64 rows) + B (128 rows), 64B/row, swizzled 16B chunks
    const int lr = tid >> 2;         // 0..63
    const int cc = tid & 3;
    auto load_chunk = [&](int chunk) {
        if (chunk < NK) {
            uint32_t st = tiles + (uint32_t)(chunk % STAGES) * STAGE_BYTES;
            const size_t gofs = (size_t)chunk * BK + cc * 8;
            uint32_t sw = (uint32_t)((cc ^ ((lr >> 1) & 3)) << 4);
            uint32_t rowb = (uint32_t)lr * 64u;
            cp16(st + rowb + sw, Ah + arow + (size_t)lr * KDIM + gofs);
            cp16(st + APLANE + rowb + sw, Bh + brow + (size_t)lr * KDIM + gofs);
            int r2 = lr + 64;
            uint32_t sw2 = (uint32_t)((cc ^ ((r2 >> 1) & 3)) << 4);
            uint32_t rowb2 = (uint32_t)r2 * 64u;
            cp16(st + APLANE + rowb2 + sw2, Bh + brow + (size_t)r2 * KDIM + gofs);
        }
        cp_commit();
    };

#pragma unroll
    for (int c0 = 0; c0 < STAGES - 1; c0++) load_chunk(c0);

    // ldmatrix lane->row/chunk mapping (m16n8k16 fragment layouts)
    const int aR = warp_m * 32 + (lane & 7) + ((lane >> 3) & 1) * 8;
    const int aC = lane >> 4;
    const int bR = warp_n * 32 + (lane & 7) + ((lane >> 4) << 3);
    const int bC = (lane >> 3) & 1;

    // double-buffered fragments
    uint32_t ahf[2][2][4], bhf[2][4][2];

    auto ldfrags = [&](int buf, uint32_t st, int ks) {
#pragma unroll
        for (int tm = 0; tm < 2; tm++) {
            int row = aR + tm * 16;
            uint32_t cidx = (uint32_t)((ks * 2 + aC) ^ ((row >> 1) & 3));
            uint32_t ad = st + (uint32_t)row * 64u + (cidx << 4);
            LDM4(ahf[buf][tm][0], ahf[buf][tm][1], ahf[buf][tm][2], ahf[buf][tm][3], ad);
        }
#pragma unroll
        for (int p = 0; p < 2; p++) {
            int row = bR + p * 16;
            uint32_t cidx = (uint32_t)((ks * 2 + bC) ^ ((row >> 1) & 3));
            uint32_t bd = st + APLANE + (uint32_t)row * 64u + (cidx << 4);
            uint32_t r0, r1, r2, r3;
            LDM4(r0, r1, r2, r3, bd);
            bhf[buf][2 * p][0] = r0; bhf[buf][2 * p][1] = r1;
            bhf[buf][2 * p + 1][0] = r2; bhf[buf][2 * p + 1][1] = r3;
        }
    };

    auto mma_pass = [&](int buf) {
#pragma unroll
        for (int tm = 0; tm < 2; tm++)
#pragma unroll
            for (int tn = 0; tn < 4; tn++)
                MMA(c[tm][tn], ahf[buf][tm], bhf[buf][tn][0], bhf[buf][tn][1]);
    };

    cp_wait2();             // chunk 0 arrived (3 groups committed, <=2 pending)
    __syncthreads();
    ldfrags(0, tiles, 0);   // chunk 0, ks=0

#pragma unroll 1
    for (int k = 0; k < NK; k++) {
        uint32_t st = tiles + (uint32_t)(k % STAGES) * STAGE_BYTES;
        ldfrags(1, st, 1);              // ks=1 frags: overlaps with buf0 MMAs below
        mma_pass(0);
        cp_wait1();                     // chunk k+1 arrived
        __syncthreads();                // all warps done reading chunk k-1 stage
        load_chunk(k + STAGES - 1);     // refill stage (k-1)%4 with chunk k+3
        if (k + 1 < NK) {
            uint32_t st2 = tiles + (uint32_t)((k + 1) % STAGES) * STAGE_BYTES;
            ldfrags(0, st2, 0);         // prefetch next chunk ks=0: overlaps buf1 MMAs
        }
        mma_pass(1);
    }

    // ---- epilogue ----
    int r0 = mtile * BM + warp_m * 32 + (lane >> 2);
    int col0 = ntile * BN + warp_n * 32 + (lane & 3) * 2;
#pragma unroll
    for (int tm = 0; tm < 2; tm++)
#pragma unroll
        for (int tn = 0; tn < 4; tn++) {
            int r = r0 + tm * 16, ccc = col0 + tn * 8;
            float* v = c[tm][tn];
            if (PACK) {
#pragma unroll
                for (int h = 0; h < 2; h++) {
                    size_t off = (size_t)(r + h * 8) * KDIM + ccc;
                    *(__half2*)(Oh + off) =
                        __halves2half2(__float2half_rn(v[2 * h]), __float2half_rn(v[2 * h + 1]));
                }
            } else {
                *(float2*)(out + (size_t)r * KDIM + ccc) = make_float2(v[0], v[1]);
                *(float2*)(out + (size_t)(r + 8) * KDIM + ccc) = make_float2(v[2], v[3]);
            }
        }
}

// ---------------- launch ----------------
// out = X * (W0*W1*W2), all GEMMs plain fp16 with fp32 accumulate:
//   P1 = fp16(W0) * fp16(W1^T)^T
//   Q  = (P1*W2)^T : Q[j][t2] = sum_t W2^T[j][t]*P1[t2][t]
//   out[i][j] = sum_k fp16(X)[i][k]*Q[j][k]
extern "C" void kernel_launch(void* const* d_in, const int* in_sizes, int n_in,
                              void* d_out, int out_size) {
    const float* x0 = (const float*)d_in[0];
    const float* x1 = (const float*)d_in[1];
    const float* W0 = (const float*)d_in[2];
    const float* W1 = (const float*)d_in[3];
    const float* W2 = (const float*)d_in[4];
    float* out = (float*)d_out;

    cudaFuncSetAttribute(gemm_kernel<true, 5>,
                         cudaFuncAttributeMaxDynamicSharedMemorySize, SMEM_DYN);
    cudaFuncSetAttribute(gemm_kernel<false, 6>,
                         cudaFuncAttributeMaxDynamicSharedMemorySize, SMEM_DYN);

    pack_all_kernel<<<20480, 256>>>(x0, x1, W0, W1, W2);
    gemm_kernel<true, 5><<<32 * 16, 256, SMEM_DYN>>>(OFF_A0, OFF_B1, OFF_P1, nullptr);
    gemm_kernel<true, 5><<<32 * 16, 256, SMEM_DYN>>>(OFF_A2, OFF_P1, OFF_Q, nullptr);
    gemm_kernel<false, 6><<<64 * 16, 256, SMEM_DYN>>>(OFF_X, OFF_Q, 0, out);
}

// round 14
// speedup vs baseline: 4.4021x; 1.0372x over previous
#include <cuda_runtime.h>
#include <cuda_fp16.h>
#include <cstdint>
#include <cstddef>

#define DI __device__ __forceinline__

// ---------------- problem constants ----------------
constexpr int KDIM  = 2048;           // K == N for every GEMM
constexpr int BM = 64, BN = 256, BK = 32;
constexpr int NK = KDIM / BK;         // 64 k-chunks
constexpr int STAGES = 4;
constexpr uint32_t APLANE = BM * 64u;                 // 4096 B
constexpr uint32_t BPLANE = BN * 64u;                 // 16384 B
constexpr uint32_t STAGE_BYTES = APLANE + BPLANE;     // 20480
constexpr uint32_t SMEM_DYN = STAGES * STAGE_BYTES + 128;   // ~82KB -> 2 CTAs/SM

// ---------------- plane pool (all tensors single fp16 plane) ----------------
constexpr size_t MEG = 1024ull * 1024ull;
constexpr size_t OFF_X  = 0;          // fp16(concat(x0,x1)) [4096 x 2048]
constexpr size_t OFF_A0 = 8 * MEG;    // fp16(W0) row-major  [2048 x 2048]
constexpr size_t OFF_B1 = 12 * MEG;   // fp16(W1^T)          [2048 x 2048]
constexpr size_t OFF_A2 = 16 * MEG;   // fp16(W2^T)          [2048 x 2048]
constexpr size_t OFF_P1 = 20 * MEG;   // P1 = W0*W1          [2048 x 2048]
constexpr size_t OFF_Q  = 24 * MEG;   // Q  = (W0*W1*W2)^T   [2048 x 2048]
constexpr size_t POOL   = 28 * MEG;

__device__ __half g_H[POOL];          // fp16 planes

// ---------------- helpers ----------------
DI uint32_t s2u(const void* p) {
    uint32_t r;
    asm("{ .reg .u64 t; cvta.to.shared.u64 t, %1; cvt.u32.u64 %0, t; }" : "=r"(r) : "l"(p));
    return r;
}
DI void cp16(uint32_t dst, const void* src) {
    asm volatile(
        "{ .reg .u64 g; cvta.to.global.u64 g, %1; cp.async.cg.shared.global [%0], [g], 16; }"
        :: "r"(dst), "l"(src) : "memory");
}
DI void cp_commit() { asm volatile("cp.async.commit_group;" ::: "memory"); }
DI void cp_wait1()  { asm volatile("cp.async.wait_group 1;" ::: "memory"); }
DI void cp_wait2()  { asm volatile("cp.async.wait_group 2;" ::: "memory"); }

#define LDM4(R0, R1, R2, R3, ADDR) \
    asm volatile("ldmatrix.sync.aligned.m8n8.x4.shared.b16 {%0,%1,%2,%3}, [%4];" \
                 : "=r"(R0), "=r"(R1), "=r"(R2), "=r"(R3) : "r"(ADDR))

#define MMA(C, A, B0, B1) \
    asm volatile("mma.sync.aligned.m16n8k16.row.col.f32.f16.f16.f32 " \
                 "{%0,%1,%2,%3},{%4,%5,%6,%7},{%8,%9},{%0,%1,%2,%3};" \
                 : "+f"((C)[0]), "+f"((C)[1]), "+f"((C)[2]), "+f"((C)[3]) \
                 : "r"((A)[0]), "r"((A)[1]), "r"((A)[2]), "r"((A)[3]), "r"(B0), "r"(B1))

// ============ fused prologue: all packing in ONE kernel ============
__global__ void pack_all_kernel(const float* __restrict__ x0, const float* __restrict__ x1,
                                const float* __restrict__ W0, const float* __restrict__ W1,
                                const float* __restrict__ W2) {
    __shared__ float s[32][33];
    int b = blockIdx.x, tid = threadIdx.x;
    if (b < 12288) {
        const float* src;
        size_t off;
        if (b < 8192) {
            int id = b * 256 + tid;
            int m = id >> 9;
            int c4 = (id & 511) * 4;
            src = (c4 < 1024) ? (x0 + (size_t)m * 1024 + c4)
                              : (x1 + (size_t)m * 1024 + (c4 - 1024));
            off = OFF_X + (size_t)m * KDIM + c4;
        } else {
            int id = (b - 8192) * 256 + tid;
            int m = id >> 9;
            int c4 = (id & 511) * 4;
            src = W0 + (size_t)m * KDIM + c4;
            off = OFF_A0 + (size_t)m * KDIM + c4;
        }
        float4 v = *(const float4*)src;
        *(__half2*)(&g_H[off])     = __halves2half2(__float2half_rn(v.x), __float2half_rn(v.y));
        *(__half2*)(&g_H[off + 2]) = __halves2half2(__float2half_rn(v.z), __float2half_rn(v.w));
    } else {
        const float* W = (b < 16384) ? W1 : W2;
        size_t dstoff = (b < 16384) ? OFF_B1 : OFF_A2;
        int bb = (b < 16384) ? (b - 12288) : (b - 16384);
        int n0 = (bb & 63) * 32, k0 = (bb >> 6) * 32;
        int tx = tid & 31, ty = tid >> 5;     // (32, 8)
#pragma unroll
        for (int i = 0; i < 4; i++)
            s[ty + i * 8][tx] = W[(size_t)(k0 + ty + i * 8) * KDIM + n0 + tx];
        __syncthreads();
#pragma unroll
        for (int i = 0; i < 4; i++) {
            float v = s[tx][ty + i * 8];      // (k_local=tx, n_local=ty+8i)
            size_t off = dstoff + (size_t)(n0 + ty + i * 8) * KDIM + k0 + tx;
            g_H[off] = __float2half_rn(v);
        }
    }
}

// ============ main GEMM: C = Ah @ Bh^T (plain fp16, fp32 accumulate) ============
// CTA tile 64x256, warp grid 2x4, warp tile 32x64 (192 smem-bytes per MMA)
template <bool PACK, int MSHIFT>
__global__ void __launch_bounds__(256, 2)
gemm_kernel(size_t aoff, size_t boff, size_t ooff, float* __restrict__ out) {
    extern __shared__ uint8_t smem[];
    uint32_t tiles = (s2u(smem) + 127u) & ~127u;

    const __half* Ah = g_H + aoff;
    const __half* Bh = g_H + boff;
    __half* Oh = g_H + ooff;

    int tid = threadIdx.x, lane = tid & 31, wid = tid >> 5;
    int warp_m = wid >> 2, warp_n = wid & 3;            // 2 x 4 warp grid, 32x64 tiles
    int mtile = blockIdx.x & ((1 << MSHIFT) - 1), ntile = blockIdx.x >> MSHIFT;

    const size_t arow = (size_t)mtile * BM * KDIM;
    const size_t brow = (size_t)ntile * BN * KDIM;

    float c[2][8][4];
#pragma unroll
    for (int a = 0; a < 2; a++)
#pragma unroll
        for (int b = 0; b < 8; b++)
#pragma unroll
            for (int d = 0; d < 4; d++) c[a][b][d] = 0.f;

    // per-chunk loader: A (64 rows) + B (256 rows), 64B/row, swizzled 16B chunks
    const int lr = tid >> 2;         // 0..63
    const int cc = tid & 3;
    auto load_chunk = [&](int chunk) {
        if (chunk < NK) {
            uint32_t st = tiles + (uint32_t)(chunk % STAGES) * STAGE_BYTES;
            const size_t gofs = (size_t)chunk * BK + cc * 8;
            uint32_t sw = (uint32_t)((cc ^ ((lr >> 1) & 3)) << 4);
            cp16(st + (uint32_t)lr * 64u + sw, Ah + arow + (size_t)lr * KDIM + gofs);
#pragma unroll
            for (int j = 0; j < 4; j++) {
                int r2 = lr + j * 64;
                uint32_t sw2 = (uint32_t)((cc ^ ((r2 >> 1) & 3)) << 4);
                cp16(st + APLANE + (uint32_t)r2 * 64u + sw2,
                     Bh + brow + (size_t)r2 * KDIM + gofs);
            }
        }
        cp_commit();
    };

#pragma unroll
    for (int c0 = 0; c0 < STAGES - 1; c0++) load_chunk(c0);

    // ldmatrix lane->row/chunk mapping (m16n8k16 fragment layouts)
    const int aR = warp_m * 32 + (lane & 7) + ((lane >> 3) & 1) * 8;
    const int aC = lane >> 4;
    const int bR = warp_n * 64 + (lane & 7) + ((lane >> 4) << 3);
    const int bC = (lane >> 3) & 1;

    // double-buffered fragments
    uint32_t ahf[2][2][4], bhf[2][8][2];

    auto ldfrags = [&](int buf, uint32_t st, int ks) {
#pragma unroll
        for (int tm = 0; tm < 2; tm++) {
            int row = aR + tm * 16;
            uint32_t cidx = (uint32_t)((ks * 2 + aC) ^ ((row >> 1) & 3));
            uint32_t ad = st + (uint32_t)row * 64u + (cidx << 4);
            LDM4(ahf[buf][tm][0], ahf[buf][tm][1], ahf[buf][tm][2], ahf[buf][tm][3], ad);
        }
#pragma unroll
        for (int p = 0; p < 4; p++) {
            int row = bR + p * 16;
            uint32_t cidx = (uint32_t)((ks * 2 + bC) ^ ((row >> 1) & 3));
            uint32_t bd = st + APLANE + (uint32_t)row * 64u + (cidx << 4);
            uint32_t r0, r1, r2, r3;
            LDM4(r0, r1, r2, r3, bd);
            bhf[buf][2 * p][0] = r0; bhf[buf][2 * p][1] = r1;
            bhf[buf][2 * p + 1][0] = r2; bhf[buf][2 * p + 1][1] = r3;
        }
    };

    auto mma_pass = [&](int buf) {
#pragma unroll
        for (int tm = 0; tm < 2; tm++)
#pragma unroll
            for (int tn = 0; tn < 8; tn++)
                MMA(c[tm][tn], ahf[buf][tm], bhf[buf][tn][0], bhf[buf][tn][1]);
    };

    cp_wait2();             // chunk 0 arrived (3 groups committed, <=2 pending)
    __syncthreads();
    ldfrags(0, tiles, 0);   // chunk 0, ks=0

#pragma unroll 1
    for (int k = 0; k < NK; k++) {
        uint32_t st = tiles + (uint32_t)(k % STAGES) * STAGE_BYTES;
        ldfrags(1, st, 1);              // ks=1 frags: overlaps with buf0 MMAs below
        mma_pass(0);
        cp_wait1();                     // chunk k+1 arrived
        __syncthreads();                // all warps done reading chunk k-1 stage
        load_chunk(k + STAGES - 1);     // refill stage (k-1)%4 with chunk k+3
        if (k + 1 < NK) {
            uint32_t st2 = tiles + (uint32_t)((k + 1) % STAGES) * STAGE_BYTES;
            ldfrags(0, st2, 0);         // prefetch next chunk ks=0: overlaps buf1 MMAs
        }
        mma_pass(1);
    }

    // ---- epilogue ----
    int r0 = mtile * BM + warp_m * 32 + (lane >> 2);
    int col0 = ntile * BN + warp_n * 64 + (lane & 3) * 2;
#pragma unroll
    for (int tm = 0; tm < 2; tm++)
#pragma unroll
        for (int tn = 0; tn < 8; tn++) {
            int r = r0 + tm * 16, ccc = col0 + tn * 8;
            float* v = c[tm][tn];
            if (PACK) {
#pragma unroll
                for (int h = 0; h < 2; h++) {
                    size_t off = (size_t)(r + h * 8) * KDIM + ccc;
                    *(__half2*)(Oh + off) =
                        __halves2half2(__float2half_rn(v[2 * h]), __float2half_rn(v[2 * h + 1]));
                }
            } else {
                *(float2*)(out + (size_t)r * KDIM + ccc) = make_float2(v[0], v[1]);
                *(float2*)(out + (size_t)(r + 8) * KDIM + ccc) = make_float2(v[2], v[3]);
            }
        }
}

// ---------------- launch ----------------
// out = X * (W0*W1*W2), all GEMMs plain fp16 with fp32 accumulate:
//   P1 = fp16(W0) * fp16(W1^T)^T
//   Q  = (P1*W2)^T : Q[j][t2] = sum_t W2^T[j][t]*P1[t2][t]
//   out[i][j] = sum_k fp16(X)[i][k]*Q[j][k]
extern "C" void kernel_launch(void* const* d_in, const int* in_sizes, int n_in,
                              void* d_out, int out_size) {
    const float* x0 = (const float*)d_in[0];
    const float* x1 = (const float*)d_in[1];
    const float* W0 = (const float*)d_in[2];
    const float* W1 = (const float*)d_in[3];
    const float* W2 = (const float*)d_in[4];
    float* out = (float*)d_out;

    cudaFuncSetAttribute(gemm_kernel<true, 5>,
                         cudaFuncAttributeMaxDynamicSharedMemorySize, SMEM_DYN);
    cudaFuncSetAttribute(gemm_kernel<false, 6>,
                         cudaFuncAttributeMaxDynamicSharedMemorySize, SMEM_DYN);

    pack_all_kernel<<<20480, 256>>>(x0, x1, W0, W1, W2);
    // weight GEMMs: 32 mtiles x 8 ntiles = 256 CTAs (one wave at occ 2)
    gemm_kernel<true, 5><<<32 * 8, 256, SMEM_DYN>>>(OFF_A0, OFF_B1, OFF_P1, nullptr);
    gemm_kernel<true, 5><<<32 * 8, 256, SMEM_DYN>>>(OFF_A2, OFF_P1, OFF_Q, nullptr);
    // final GEMM: 64 mtiles x 8 ntiles = 512 CTAs
    gemm_kernel<false, 6><<<64 * 8, 256, SMEM_DYN>>>(OFF_X, OFF_Q, 0, out);
}